// round 13
// baseline (speedup 1.0000x reference)
#include <cuda_runtime.h>
#include <math.h>
#include <stdint.h>

// ---------------- problem constants ----------------
#define BB 32
#define MM 512
#define DD 512
#define HH 8
#define FF 8
#define CC 64           // DD / FF
#define TDD 4096        // FF * MM
#define MD (MM * DD)    // 262144

// ---------------- device scratch (no allocs allowed) ----------------
__device__ float g_x1 [(size_t)BB * MD];
__device__ float g_q  [(size_t)HH * BB * MD];
__device__ float g_k  [(size_t)HH * BB * MD];
__device__ float g_v  [(size_t)HH * BB * MD];
__device__ float g_s  [(size_t)HH * BB * MM * MM];
__device__ float g_cat[(size_t)BB * MM * HH * DD];
__device__ float g_x2 [(size_t)BB * MD];
__device__ float g_x3 [(size_t)BB * MD];
__device__ float g_t  [(size_t)BB * CC * TDD];
__device__ float g_tq [(size_t)BB * CC * TDD];
__device__ float g_tk [(size_t)BB * CC * TDD];
__device__ float g_tv [(size_t)BB * CC * TDD];
__device__ float g_s2 [(size_t)BB * CC * CC];
__device__ float g_s2p[(size_t)8 * BB * CC * CC];
__device__ float g_t2 [(size_t)BB * CC * TDD];
__device__ float g_ff [BB];
// tf32-rounded, TRANSPOSED weight copies (B operands, [n][k] layout)
__device__ float g_rwqT[(size_t)HH * DD * DD];
__device__ float g_rwkT[(size_t)HH * DD * DD];
__device__ float g_rwvT[(size_t)HH * DD * DD];
__device__ float g_rlwT[(size_t)HH * DD * DD];      // [512][4096]
__device__ float g_rtwqT[(size_t)TDD * TDD];
__device__ float g_rtwkT[(size_t)TDD * TDD];
__device__ float g_rtwvT[(size_t)TDD * TDD];

// ---------------- tf32 helpers ----------------
__device__ __forceinline__ uint32_t f2tf(float f) {
    uint32_t r;
    asm("cvt.rna.tf32.f32 %0, %1;" : "=r"(r) : "f"(f));
    return r;
}
__device__ __forceinline__ float rndtf(float f) { return __uint_as_float(f2tf(f)); }

__device__ __forceinline__ uint32_t cvta_smem_u32(const void* p) {
    uint32_t r;
    asm("{ .reg .u64 t; cvta.to.shared.u64 t, %1; cvt.u32.u64 %0, t; }" : "=r"(r) : "l"(p));
    return r;
}
__device__ __forceinline__ void ldsm4(uint32_t r[4], uint32_t addr) {
    asm volatile("ldmatrix.sync.aligned.m8n8.x4.shared.b16 {%0,%1,%2,%3}, [%4];"
                 : "=r"(r[0]), "=r"(r[1]), "=r"(r[2]), "=r"(r[3]) : "r"(addr));
}
__device__ __forceinline__ uint32_t lds32(uint32_t addr) {
    uint32_t v;
    asm volatile("ld.shared.b32 %0, [%1];" : "=r"(v) : "r"(addr));
    return v;
}
__device__ __forceinline__ void mma_tf32(float c[4], const uint32_t a[4], uint32_t b0, uint32_t b1) {
    asm volatile("mma.sync.aligned.m16n8k8.row.col.f32.tf32.tf32.f32 "
                 "{%0,%1,%2,%3}, {%4,%5,%6,%7}, {%8,%9}, {%0,%1,%2,%3};"
                 : "+f"(c[0]), "+f"(c[1]), "+f"(c[2]), "+f"(c[3])
                 : "r"(a[0]), "r"(a[1]), "r"(a[2]), "r"(a[3]), "r"(b0), "r"(b1));
}
#define CP16(dst, src) asm volatile("cp.async.cg.shared.global [%0], [%1], 16;" :: "r"(dst), "l"(src))
#define CP_COMMIT()    asm volatile("cp.async.commit_group;")
#define CP_WAIT1()     asm volatile("cp.async.wait_group 1;")

// ---------------- tiled transpose (+optional tf32 round): out[c][r] = in[r][c] ----------------
// block (32,8), grid (C/32, R/32, batch). R,C multiples of 32.
__global__ void tpose_k(const float* __restrict__ in, float* __restrict__ out,
                        int R, int C, long sIn, long sOut, int doRound) {
    __shared__ float tile[32][33];
    const float* ib = in  + (long)blockIdx.z * sIn;
    float*       ob = out + (long)blockIdx.z * sOut;
    int c0 = blockIdx.x * 32, r0 = blockIdx.y * 32;
    #pragma unroll
    for (int y = threadIdx.y; y < 32; y += 8)
        tile[y][threadIdx.x] = ib[(long)(r0 + y) * C + c0 + threadIdx.x];
    __syncthreads();
    #pragma unroll
    for (int y = threadIdx.y; y < 32; y += 8) {
        float v = tile[threadIdx.x][y];
        ob[(long)(c0 + y) * R + r0 + threadIdx.x] = doRound ? rndtf(v) : v;
    }
}

// transpose 3 weight sets in one launch (always rounds). grid (C/32, R/32, 3*nb).
__global__ void tpose3_k(const float* __restrict__ i0, const float* __restrict__ i1,
                         const float* __restrict__ i2,
                         float* __restrict__ o0, float* __restrict__ o1, float* __restrict__ o2,
                         int R, int C, long stride, int nb) {
    __shared__ float tile[32][33];
    int z = blockIdx.z;
    int sel = z / nb, bb = z % nb;
    const float* in  = (sel == 0) ? i0 : (sel == 1) ? i1 : i2;
    float*       out = (sel == 0) ? o0 : (sel == 1) ? o1 : o2;
    const float* ib = in  + (long)bb * stride;
    float*       ob = out + (long)bb * stride;
    int c0 = blockIdx.x * 32, r0 = blockIdx.y * 32;
    #pragma unroll
    for (int y = threadIdx.y; y < 32; y += 8)
        tile[y][threadIdx.x] = ib[(long)(r0 + y) * C + c0 + threadIdx.x];
    __syncthreads();
    #pragma unroll
    for (int y = threadIdx.y; y < 32; y += 8)
        ob[(long)(c0 + y) * R + r0 + threadIdx.x] = rndtf(tile[threadIdx.x][y]);
}

// ---------------- RMSNorm ----------------
__global__ void rms_reduce_k(const float* __restrict__ x, float* __restrict__ ff) {
    int b = blockIdx.x;
    const float* xb = x + (size_t)b * MD;
    float s = 0.f;
    for (int i = threadIdx.x; i < MD; i += blockDim.x) {
        float v = xb[i];
        s += v * v;
    }
    __shared__ float sm[32];
    for (int o = 16; o; o >>= 1) s += __shfl_xor_sync(0xffffffffu, s, o);
    if ((threadIdx.x & 31) == 0) sm[threadIdx.x >> 5] = s;
    __syncthreads();
    if (threadIdx.x < 32) {
        s = (threadIdx.x < (blockDim.x >> 5)) ? sm[threadIdx.x] : 0.f;
        for (int o = 16; o; o >>= 1) s += __shfl_xor_sync(0xffffffffu, s, o);
        if (threadIdx.x == 0) ff[b] = sqrtf((float)MD) * rsqrtf(s);
    }
}

__global__ void rms_apply_k(const float* __restrict__ x, const float* __restrict__ scale,
                            const float* __restrict__ ff, float* __restrict__ y) {
    long i = (long)blockIdx.x * blockDim.x + threadIdx.x;
    if (i >= (long)BB * MD) return;
    int b  = (int)(i / MD);
    int md = (int)(i % MD);
    y[i] = rndtf(x[i] * scale[md] * ff[b]);
}

// ---------------- row softmax (warp per row), optional tf32 rounding ----------------
__global__ void softmax_k(float* __restrict__ s, int L, long nrows, int doRound) {
    long warp = (long)blockIdx.x * (blockDim.x >> 5) + (threadIdx.x >> 5);
    if (warp >= nrows) return;
    int lane = threadIdx.x & 31;
    float* row = s + warp * (long)L;
    float mx = -INFINITY;
    for (int i = lane; i < L; i += 32) mx = fmaxf(mx, row[i]);
    for (int o = 16; o; o >>= 1) mx = fmaxf(mx, __shfl_xor_sync(0xffffffffu, mx, o));
    float sum = 0.f;
    for (int i = lane; i < L; i += 32) {
        float e = __expf(row[i] - mx);
        row[i] = e;
        sum += e;
    }
    for (int o = 16; o; o >>= 1) sum += __shfl_xor_sync(0xffffffffu, sum, o);
    float inv = 1.f / sum;
    for (int i = lane; i < L; i += 32) {
        float vv = row[i] * inv;
        row[i] = doRound ? rndtf(vv) : vv;
    }
}

// ==================== tf32 mma.sync GEMM, cp.async 3-stage ====================
// Inputs already tf32-rounded fp32 bit patterns.
// C = alpha*A@op(B) (+R)(+bias), optional fused RoPE, optional round.
// A row-major [m][k]; B: TRANSB ? [n][k] (n-major smem + ldmatrix)
//                        : [k][n] (k-major smem pitch 136 + direct LDS fragments).
// 128x128x32 CTA tile, 256 thr (2m x 4n warps), warp 64x32. M,N%128==0, K%32==0, K>=64.

#define NSTG   3
#define A_STG  4096                      // u32 per stage
#define B_STG  4352                      // u32 per stage (NN needs 32x136; TRANSB uses 4096)
#define STG_U32 (A_STG + B_STG)          // 8448
#define TG_SMEM (NSTG * STG_U32 * 4)     // 101376 bytes

template<bool TRANSB, bool RES, bool BIAS, bool ROUND, bool ROPE>
__global__ void __launch_bounds__(256, 2) tg_k(
    const float* __restrict__ A, int lda, long sAo, long sAi,
    const float* __restrict__ Bm, int ldb, long sBo, long sBi,
    float*       __restrict__ Cm, int ldc, long sCo, long sCi,
    const float* __restrict__ R, int ldr, long sRi,
    const float* __restrict__ bias,
    int K, int inner, float alpha, int angmod, float thc)
{
    extern __shared__ uint32_t smem[];

    int z  = blockIdx.z;
    int zo = z / inner;
    int zi = z - zo * inner;
    A  += zo * sAo + zi * sAi;
    Bm += zo * sBo + zi * sBi;
    Cm += zo * sCo + zi * sCi;
    if (RES) R += (long)zi * sRi;

    const int tid  = threadIdx.x;
    const int lane = tid & 31;
    const int wid  = tid >> 5;
    const int warpM = wid & 1;
    const int warpN = wid >> 1;
    const int m0 = blockIdx.y << 7;
    const int n0 = blockIdx.x << 7;

    const uint32_t sbase = cvta_smem_u32(smem);

    const int cA = tid & 7;     // 16B chunk 0..7
    const int rA = tid >> 3;    // row 0..31
    const int lr = (lane & 7) + ((lane >> 3) & 1) * 8;
    const int lc = lane >> 4;
    // NN B fragment per-thread base offset (u32 units within B stage)
    const int bfrag = (lane & 3) * 136 + warpN * 32 + (lane >> 2);

    float acc[4][4][4];
    #pragma unroll
    for (int i = 0; i < 4; i++)
        #pragma unroll
        for (int j = 0; j < 4; j++)
            #pragma unroll
            for (int r = 0; r < 4; r++) acc[i][j][r] = 0.f;

    const int niter = K >> 5;

    #define TG_ISSUE(st, k0)                                                          \
    {                                                                                 \
        uint32_t sA = sbase + (uint32_t)(st) * STG_U32 * 4;                           \
        uint32_t sB = sA + A_STG * 4;                                                 \
        _Pragma("unroll")                                                             \
        for (int g = 0; g < 4; g++) {                                                 \
            int r = rA + 32 * g;                                                      \
            int ch = cA ^ (r & 7);                                                    \
            CP16(sA + (uint32_t)(r * 32 + ch * 4) * 4,                                \
                 &A[(long)(m0 + r) * lda + (k0) + cA * 4]);                           \
            if (TRANSB) {                                                             \
                CP16(sB + (uint32_t)(r * 32 + ch * 4) * 4,                            \
                     &Bm[(long)(n0 + r) * ldb + (k0) + cA * 4]);                      \
            } else {                                                                  \
                int c = cA + 8 * g;                                                   \
                CP16(sB + (uint32_t)(rA * 136 + c * 4) * 4,                           \
                     &Bm[(long)((k0) + rA) * ldb + n0 + c * 4]);                      \
            }                                                                         \
        }                                                                             \
    }

    TG_ISSUE(0, 0);  CP_COMMIT();
    TG_ISSUE(1, 32); CP_COMMIT();

    for (int it = 0; it < niter; it++) {
        CP_WAIT1();
        __syncthreads();

        int nx = it + 2;
        if (nx < niter) { TG_ISSUE(nx % NSTG, nx << 5); }
        CP_COMMIT();   // empty group near the tail keeps wait_group<1> uniform

        int st = it % NSTG;
        const uint32_t baseA = sbase + (uint32_t)st * STG_U32 * 4;
        const uint32_t baseB = baseA + A_STG * 4;
        #pragma unroll
        for (int s = 0; s < 4; s++) {
            uint32_t af[4][4];
            #pragma unroll
            for (int i = 0; i < 4; i++) {
                int row = warpM * 64 + i * 16 + lr;
                int ch  = (2 * s + lc) ^ (row & 7);
                ldsm4(af[i], baseA + (uint32_t)(row * 32 + ch * 4) * 4);
            }
            if (TRANSB) {
                uint32_t bq[2][4];
                #pragma unroll
                for (int p = 0; p < 2; p++) {
                    int row = warpN * 32 + p * 16 + lr;
                    int ch  = (2 * s + lc) ^ (row & 7);
                    ldsm4(bq[p], baseB + (uint32_t)(row * 32 + ch * 4) * 4);
                }
                #pragma unroll
                for (int i = 0; i < 4; i++)
                    #pragma unroll
                    for (int j = 0; j < 4; j++)
                        mma_tf32(acc[i][j], af[i], bq[j >> 1][j & 1], bq[j >> 1][2 + (j & 1)]);
            } else {
                uint32_t b0[4], b1[4];
                #pragma unroll
                for (int j = 0; j < 4; j++) {
                    uint32_t ad = baseB + (uint32_t)(s * 8 * 136 + bfrag + j * 8) * 4;
                    b0[j] = lds32(ad);
                    b1[j] = lds32(ad + 544 * 4);   // +4 k-rows * pitch 136
                }
                #pragma unroll
                for (int i = 0; i < 4; i++)
                    #pragma unroll
                    for (int j = 0; j < 4; j++)
                        mma_tf32(acc[i][j], af[i], b0[j], b1[j]);
            }
        }
    }
    #undef TG_ISSUE

    // --- epilogue: alpha, (RoPE), (residual/bias), (round), store ---
    const int g8 = lane >> 2;
    const int t4 = lane & 3;
    #pragma unroll
    for (int i = 0; i < 4; i++) {
        int mrow = m0 + warpM * 64 + i * 16 + g8;
        #pragma unroll
        for (int j = 0; j < 4; j++) {
            int col = n0 + warpN * 32 + j * 8 + 2 * t4;   // always even
            float v0 = acc[i][j][0] * alpha;
            float v1 = acc[i][j][1] * alpha;
            float v2 = acc[i][j][2] * alpha;
            float v3 = acc[i][j][3] * alpha;
            if (ROPE) {
                int pair = col >> 1;
                float theta = exp2f(thc * ((float)pair - 1.0f));
                float sn0, cs0, sn1, cs1;
                sincosf((float)(mrow % angmod) * theta, &sn0, &cs0);
                sincosf((float)((mrow + 8) % angmod) * theta, &sn1, &cs1);
                float e = v0, o = v1;
                v0 = fmaf(e, cs0, o * sn0);
                v1 = fmaf(-e, sn0, o * cs0);
                e = v2; o = v3;
                v2 = fmaf(e, cs1, o * sn1);
                v3 = fmaf(-e, sn1, o * cs1);
            }
            if (RES) {
                v0 += R[(long)mrow * ldr + col];
                v1 += R[(long)mrow * ldr + col + 1];
                v2 += R[(long)(mrow + 8) * ldr + col];
                v3 += R[(long)(mrow + 8) * ldr + col + 1];
            }
            if (BIAS) {
                v0 += bias[col]; v1 += bias[col + 1];
                v2 += bias[col]; v3 += bias[col + 1];
            }
            if (ROUND) { v0 = rndtf(v0); v1 = rndtf(v1); v2 = rndtf(v2); v3 = rndtf(v3); }
            *reinterpret_cast<float2*>(&Cm[(long)mrow * ldc + col])       = make_float2(v0, v1);
            *reinterpret_cast<float2*>(&Cm[(long)(mrow + 8) * ldc + col]) = make_float2(v2, v3);
        }
    }
}

// ================= small fp32 SGEMM: 64x64 tile (stage-2 attn) =====
template<bool TRANSB, bool RES, bool BIAS>
__global__ void __launch_bounds__(256) sgemm_k(
    const float* __restrict__ A, int lda, long sAo, long sAi,
    const float* __restrict__ Bm, int ldb, long sBo, long sBi,
    float*       __restrict__ Cm, int ldc, long sCo, long sCi,
    const float* __restrict__ R, int ldr, long sRi,
    const float* __restrict__ bias,
    int K, int inner, float alpha)
{
    int z  = blockIdx.z;
    int zo = z / inner;
    int zi = z - zo * inner;
    A  += zo * sAo + zi * sAi;
    Bm += zo * sBo + zi * sBi;
    Cm += zo * sCo + zi * sCi;
    if (RES) R += (long)zi * sRi;

    __shared__ __align__(16) float As[16][68];
    __shared__ __align__(16) float Bs[16][68];

    const int tid = threadIdx.x;
    const int m0 = blockIdx.y << 6;
    const int n0 = blockIdx.x << 6;
    const int tx = tid & 15, ty = tid >> 4;

    const int ar = tid >> 2;
    const int ac = (tid & 3) << 2;
    const int br = tid >> 4;
    const int bc = (tid & 15) << 2;

    float acc[4][4] = {};

    for (int k0 = 0; k0 < K; k0 += 16) {
        float4 av = *reinterpret_cast<const float4*>(&A[(long)(m0 + ar) * lda + k0 + ac]);
        As[ac + 0][ar] = av.x; As[ac + 1][ar] = av.y;
        As[ac + 2][ar] = av.z; As[ac + 3][ar] = av.w;
        if (!TRANSB) {
            float4 bv = *reinterpret_cast<const float4*>(&Bm[(long)(k0 + br) * ldb + n0 + bc]);
            *reinterpret_cast<float4*>(&Bs[br][bc]) = bv;
        } else {
            float4 bv = *reinterpret_cast<const float4*>(&Bm[(long)(n0 + ar) * ldb + k0 + ac]);
            Bs[ac + 0][ar] = bv.x; Bs[ac + 1][ar] = bv.y;
            Bs[ac + 2][ar] = bv.z; Bs[ac + 3][ar] = bv.w;
        }
        __syncthreads();
        #pragma unroll
        for (int k = 0; k < 16; k++) {
            float4 a4 = *reinterpret_cast<const float4*>(&As[k][ty << 2]);
            float4 b4 = *reinterpret_cast<const float4*>(&Bs[k][tx << 2]);
            float a[4] = {a4.x, a4.y, a4.z, a4.w};
            float b[4] = {b4.x, b4.y, b4.z, b4.w};
            #pragma unroll
            for (int i = 0; i < 4; i++)
                #pragma unroll
                for (int j = 0; j < 4; j++)
                    acc[i][j] = fmaf(a[i], b[j], acc[i][j]);
        }
        __syncthreads();
    }

    #pragma unroll
    for (int i = 0; i < 4; i++) {
        int m = m0 + (ty << 2) + i;
        #pragma unroll
        for (int j = 0; j < 4; j++) {
            int n = n0 + (tx << 2) + j;
            float v = acc[i][j] * alpha;
            if (RES)  v += R[(long)m * ldr + n];
            if (BIAS) v += bias[n];
            Cm[(long)m * ldc + n] = v;
        }
    }
}

// ---------------- stage-2 split-K reduce ----------------
__global__ void s2red_k(const float* __restrict__ p, float* __restrict__ o) {
    long i = (long)blockIdx.x * blockDim.x + threadIdx.x;
    if (i >= (long)BB * CC * CC) return;
    float s = 0.f;
    #pragma unroll
    for (int ks = 0; ks < 8; ks++) s += p[(long)ks * BB * CC * CC + i];
    o[i] = s;
}

// ---------------- launch ----------------
extern "C" void kernel_launch(void* const* d_in, const int* in_sizes, int n_in,
                              void* d_out, int out_size) {
    const float* x     = (const float*)d_in[0];
    const float* scale = (const float*)d_in[1];
    const float* wq    = (const float*)d_in[2];
    const float* wk    = (const float*)d_in[3];
    const float* wv    = (const float*)d_in[4];
    const float* lin_w = (const float*)d_in[5];
    const float* lin_b = (const float*)d_in[6];
    const float* twq   = (const float*)d_in[7];
    const float* twk   = (const float*)d_in[8];
    const float* twv   = (const float*)d_in[9];
    float* out = (float*)d_out;

    float *x1, *q, *k, *v, *s, *cat, *x2, *x3, *t, *tq, *tk, *tv, *s2, *s2p, *t2, *ff;
    float *rwqT, *rwkT, *rwvT, *rlwT, *rtwqT, *rtwkT, *rtwvT;
    cudaGetSymbolAddress((void**)&x1,  g_x1);
    cudaGetSymbolAddress((void**)&q,   g_q);
    cudaGetSymbolAddress((void**)&k,   g_k);
    cudaGetSymbolAddress((void**)&v,   g_v);
    cudaGetSymbolAddress((void**)&s,   g_s);
    cudaGetSymbolAddress((void**)&cat, g_cat);
    cudaGetSymbolAddress((void**)&x2,  g_x2);
    cudaGetSymbolAddress((void**)&x3,  g_x3);
    cudaGetSymbolAddress((void**)&t,   g_t);
    cudaGetSymbolAddress((void**)&tq,  g_tq);
    cudaGetSymbolAddress((void**)&tk,  g_tk);
    cudaGetSymbolAddress((void**)&tv,  g_tv);
    cudaGetSymbolAddress((void**)&s2,  g_s2);
    cudaGetSymbolAddress((void**)&s2p, g_s2p);
    cudaGetSymbolAddress((void**)&t2,  g_t2);
    cudaGetSymbolAddress((void**)&ff,  g_ff);
    cudaGetSymbolAddress((void**)&rwqT, g_rwqT);
    cudaGetSymbolAddress((void**)&rwkT, g_rwkT);
    cudaGetSymbolAddress((void**)&rwvT, g_rwvT);
    cudaGetSymbolAddress((void**)&rlwT, g_rlwT);
    cudaGetSymbolAddress((void**)&rtwqT, g_rtwqT);
    cudaGetSymbolAddress((void**)&rtwkT, g_rtwkT);
    cudaGetSymbolAddress((void**)&rtwvT, g_rtwvT);

    cudaFuncSetAttribute(tg_k<true ,false,false,true ,true >, cudaFuncAttributeMaxDynamicSharedMemorySize, TG_SMEM);
    cudaFuncSetAttribute(tg_k<true ,false,false,true ,false>, cudaFuncAttributeMaxDynamicSharedMemorySize, TG_SMEM);
    cudaFuncSetAttribute(tg_k<true ,false,false,false,false>, cudaFuncAttributeMaxDynamicSharedMemorySize, TG_SMEM);
    cudaFuncSetAttribute(tg_k<true ,false,false,false,true >, cudaFuncAttributeMaxDynamicSharedMemorySize, TG_SMEM);
    cudaFuncSetAttribute(tg_k<true ,true ,true ,false,false>, cudaFuncAttributeMaxDynamicSharedMemorySize, TG_SMEM);
    cudaFuncSetAttribute(tg_k<false,false,false,true ,false>, cudaFuncAttributeMaxDynamicSharedMemorySize, TG_SMEM);

    const float th1 = -2.0f * log2f(10000.0f) / (float)DD;
    const float th2 = -2.0f * log2f(10000.0f) / (float)TDD;
    const float al1 = 1.0f / sqrtf((float)DD);
    const float al2 = 1.0f / sqrtf((float)TDD);

    // ---- launches 0-2: weight round+transpose (B operands become [n][k]) ----
    {
        dim3 b32(32, 8);
        tpose3_k<<<dim3(DD/32, DD/32, 3*HH), b32>>>(wq, wk, wv, rwqT, rwkT, rwvT,
                                                    DD, DD, (long)DD*DD, HH);
        tpose_k<<<dim3(DD/32, (HH*DD)/32, 1), b32>>>(lin_w, rlwT, HH*DD, DD, 0, 0, 1);
        tpose3_k<<<dim3(TDD/32, TDD/32, 3), b32>>>(twq, twk, twv, rtwqT, rtwkT, rtwvT,
                                                   TDD, TDD, 0, 1);
    }

    // ---- launches 3-4: x1 = rmsnorm(x) (tf32-rounded) ----
    rms_reduce_k<<<BB, 1024>>>(x, ff);
    rms_apply_k<<<(BB * MD) / 256, 256>>>(x, scale, ff, x1);

    // ---- launch 5 (ncu capture slot): q GEMM ----
    // 2) q/k/v[h,b] = x1[b] @ wT[h]^T   (q,k with fused RoPE; all rounded)
    {
        dim3 g(DD / 128, MM / 128, HH * BB);
        tg_k<true,false,false,true,true ><<<g, 256, TG_SMEM>>>(x1, DD, 0, MD, rwqT, DD, (long)DD*DD, 0,
                                                               q, DD, (long)BB * MD, MD,
                                                               nullptr, 0, 0, nullptr, DD, BB, 1.f, MM, th1);
        tg_k<true,false,false,true,true ><<<g, 256, TG_SMEM>>>(x1, DD, 0, MD, rwkT, DD, (long)DD*DD, 0,
                                                               k, DD, (long)BB * MD, MD,
                                                               nullptr, 0, 0, nullptr, DD, BB, 1.f, MM, th1);
        tg_k<true,false,false,true,false><<<g, 256, TG_SMEM>>>(x1, DD, 0, MD, rwvT, DD, (long)DD*DD, 0,
                                                               v, DD, (long)BB * MD, MD,
                                                               nullptr, 0, 0, nullptr, DD, BB, 1.f, 1, 0.f);
    }

    // 4) S = (q@k^T)/sqrt(D); softmax (rounded); O = P @ v (NN, rounded, into cat layout)
    {
        dim3 g(MM / 128, MM / 128, HH * BB);
        tg_k<true,false,false,false,false><<<g, 256, TG_SMEM>>>(q, DD, (long)BB * MD, MD,
                                                                k, DD, (long)BB * MD, MD,
                                                                s, MM, (long)BB * MM * MM, (long)MM * MM,
                                                                nullptr, 0, 0, nullptr, DD, BB, al1, 1, 0.f);
        long nrows = (long)HH * BB * MM;
        softmax_k<<<(int)(nrows / 8), 256>>>(s, MM, nrows, 1);
        dim3 g2(DD / 128, MM / 128, HH * BB);
        tg_k<false,false,false,true,false><<<g2, 256, TG_SMEM>>>(s, MM, (long)BB * MM * MM, (long)MM * MM,
                                                                 v, DD, (long)BB * MD, MD,
                                                                 cat, HH * DD, (long)DD, (long)MM * HH * DD,
                                                                 nullptr, 0, 0, nullptr, MM, BB, 1.f, 1, 0.f);
    }

    // 5) x2 = x1 + cat @ rlwT^T + lin_b   (no round; feeds rmsnorm only)
    {
        dim3 g(DD / 128, (BB * MM) / 128, 1);
        tg_k<true,true,true,false,false><<<g, 256, TG_SMEM>>>(cat, HH * DD, 0, 0, rlwT, HH * DD, 0, 0,
                                                              x2, DD, 0, 0,
                                                              x1, DD, 0, lin_b, HH * DD, 1, 1.f, 1, 0.f);
    }

    // 6) x3 = rmsnorm(x2)  (rounded)
    rms_reduce_k<<<BB, 1024>>>(x2, ff);
    rms_apply_k<<<(BB * MD) / 256, 256>>>(x2, scale, ff, x3);

    // 7) t = per-batch 512x512 transpose of x3  (channel shuffle == plain transpose)
    tpose_k<<<dim3(DD/32, MM/32, BB), dim3(32,8)>>>(x3, t, MM, DD, (long)MD, (long)MD, 0);

    // 8) tq/tk/tv = t @ rtwT^T  (tq,tk with fused stage-2 RoPE; no round, feed fp32 stage-2)
    {
        dim3 g(TDD / 128, (BB * CC) / 128, 1);
        tg_k<true,false,false,false,true ><<<g, 256, TG_SMEM>>>(t, TDD, 0, 0, rtwqT, TDD, 0, 0, tq, TDD, 0, 0,
                                                                nullptr, 0, 0, nullptr, TDD, 1, 1.f, CC, th2);
        tg_k<true,false,false,false,true ><<<g, 256, TG_SMEM>>>(t, TDD, 0, 0, rtwkT, TDD, 0, 0, tk, TDD, 0, 0,
                                                                nullptr, 0, 0, nullptr, TDD, 1, 1.f, CC, th2);
        tg_k<true,false,false,false,false><<<g, 256, TG_SMEM>>>(t, TDD, 0, 0, rtwvT, TDD, 0, 0, tv, TDD, 0, 0,
                                                                nullptr, 0, 0, nullptr, TDD, 1, 1.f, 1, 0.f);
    }

    // 10) S2 = (tq @ tk^T)/64 via split-K 8; reduce; softmax; t2 = t + P2 @ tv
    {
        dim3 g(1, 1, 8 * BB);       // zo = K-split index, zi = batch
        sgemm_k<true,false,false><<<g, 256>>>(tq, TDD, 512, (long)CC * TDD,
                                              tk, TDD, 512, (long)CC * TDD,
                                              s2p, CC, (long)BB * CC * CC, (long)CC * CC,
                                              nullptr, 0, 0, nullptr, 512, BB, al2);
        s2red_k<<<(BB * CC * CC + 255) / 256, 256>>>(s2p, s2);
        softmax_k<<<(BB * CC) / 8, 256>>>(s2, CC, (long)BB * CC, 0);
        dim3 g2(TDD / 64, 1, BB);
        sgemm_k<false,true,false><<<g2, 256>>>(s2, CC, 0, (long)CC * CC,
                                               tv, TDD, 0, (long)CC * TDD,
                                               t2, TDD, 0, (long)CC * TDD,
                                               t, TDD, (long)CC * TDD, nullptr,
                                               CC, BB, 1.f);
    }

    // 11) out = per-batch transpose of t2 back to [m][d]
    tpose_k<<<dim3(MM/32, DD/32, BB), dim3(32,8)>>>(t2, out, DD, MM, (long)MD, (long)MD, 0);
}

// round 14
// speedup vs baseline: 1.0177x; 1.0177x over previous
#include <cuda_runtime.h>
#include <math.h>
#include <stdint.h>

// ---------------- problem constants ----------------
#define BB 32
#define MM 512
#define DD 512
#define HH 8
#define FF 8
#define CC 64           // DD / FF
#define TDD 4096        // FF * MM
#define MD (MM * DD)    // 262144

// ---------------- device scratch (no allocs allowed) ----------------
__device__ float g_x1 [(size_t)BB * MD];
__device__ float g_q  [(size_t)HH * BB * MD];
__device__ float g_k  [(size_t)HH * BB * MD];
__device__ float g_v  [(size_t)HH * BB * MD];
__device__ float g_s  [(size_t)HH * BB * MM * MM];
__device__ float g_cat[(size_t)BB * MM * HH * DD];
__device__ float g_x2 [(size_t)BB * MD];
__device__ float g_x3 [(size_t)BB * MD];
__device__ float g_t  [(size_t)BB * CC * TDD];
__device__ float g_tq [(size_t)BB * CC * TDD];
__device__ float g_tk [(size_t)BB * CC * TDD];
__device__ float g_tv [(size_t)BB * CC * TDD];
__device__ float g_s2 [(size_t)BB * CC * CC];
__device__ float g_s2p[(size_t)8 * BB * CC * CC];
__device__ float g_t2 [(size_t)BB * CC * TDD];
__device__ float g_ff [BB];
__device__ float g_red[BB * 32];
// tf32-rounded, TRANSPOSED weight copies (B operands, [n][k] layout)
__device__ float g_rwqT[(size_t)HH * DD * DD];
__device__ float g_rwkT[(size_t)HH * DD * DD];
__device__ float g_rwvT[(size_t)HH * DD * DD];
__device__ float g_rlwT[(size_t)HH * DD * DD];      // [512][4096]
__device__ float g_rtwqT[(size_t)TDD * TDD];
__device__ float g_rtwkT[(size_t)TDD * TDD];
__device__ float g_rtwvT[(size_t)TDD * TDD];

// ---------------- tf32 helpers ----------------
__device__ __forceinline__ uint32_t f2tf(float f) {
    uint32_t r;
    asm("cvt.rna.tf32.f32 %0, %1;" : "=r"(r) : "f"(f));
    return r;
}
__device__ __forceinline__ float rndtf(float f) { return __uint_as_float(f2tf(f)); }

__device__ __forceinline__ uint32_t cvta_smem_u32(const void* p) {
    uint32_t r;
    asm("{ .reg .u64 t; cvta.to.shared.u64 t, %1; cvt.u32.u64 %0, t; }" : "=r"(r) : "l"(p));
    return r;
}
__device__ __forceinline__ void ldsm4(uint32_t r[4], uint32_t addr) {
    asm volatile("ldmatrix.sync.aligned.m8n8.x4.shared.b16 {%0,%1,%2,%3}, [%4];"
                 : "=r"(r[0]), "=r"(r[1]), "=r"(r[2]), "=r"(r[3]) : "r"(addr));
}
__device__ __forceinline__ uint32_t lds32(uint32_t addr) {
    uint32_t v;
    asm volatile("ld.shared.b32 %0, [%1];" : "=r"(v) : "r"(addr));
    return v;
}
__device__ __forceinline__ void mma_tf32(float c[4], const uint32_t a[4], uint32_t b0, uint32_t b1) {
    asm volatile("mma.sync.aligned.m16n8k8.row.col.f32.tf32.tf32.f32 "
                 "{%0,%1,%2,%3}, {%4,%5,%6,%7}, {%8,%9}, {%0,%1,%2,%3};"
                 : "+f"(c[0]), "+f"(c[1]), "+f"(c[2]), "+f"(c[3])
                 : "r"(a[0]), "r"(a[1]), "r"(a[2]), "r"(a[3]), "r"(b0), "r"(b1));
}
#define CP16(dst, src) asm volatile("cp.async.cg.shared.global [%0], [%1], 16;" :: "r"(dst), "l"(src))
#define CP_COMMIT()    asm volatile("cp.async.commit_group;")
#define CP_WAIT1()     asm volatile("cp.async.wait_group 1;")

// ---------------- tiled transpose (+optional tf32 round): out[c][r] = in[r][c] ----------------
// block (32,8), grid (C/32, R/32, batch). R,C multiples of 32.
__global__ void tpose_k(const float* __restrict__ in, float* __restrict__ out,
                        int R, int C, long sIn, long sOut, int doRound) {
    __shared__ float tile[32][33];
    const float* ib = in  + (long)blockIdx.z * sIn;
    float*       ob = out + (long)blockIdx.z * sOut;
    int c0 = blockIdx.x * 32, r0 = blockIdx.y * 32;
    #pragma unroll
    for (int y = threadIdx.y; y < 32; y += 8)
        tile[y][threadIdx.x] = ib[(long)(r0 + y) * C + c0 + threadIdx.x];
    __syncthreads();
    #pragma unroll
    for (int y = threadIdx.y; y < 32; y += 8) {
        float v = tile[threadIdx.x][y];
        ob[(long)(c0 + y) * R + r0 + threadIdx.x] = doRound ? rndtf(v) : v;
    }
}

// transpose 3 weight sets in one launch (always rounds). grid (C/32, R/32, 3*nb).
__global__ void tpose3_k(const float* __restrict__ i0, const float* __restrict__ i1,
                         const float* __restrict__ i2,
                         float* __restrict__ o0, float* __restrict__ o1, float* __restrict__ o2,
                         int R, int C, long stride, int nb) {
    __shared__ float tile[32][33];
    int z = blockIdx.z;
    int sel = z / nb, bb = z % nb;
    const float* in  = (sel == 0) ? i0 : (sel == 1) ? i1 : i2;
    float*       out = (sel == 0) ? o0 : (sel == 1) ? o1 : o2;
    const float* ib = in  + (long)bb * stride;
    float*       ob = out + (long)bb * stride;
    int c0 = blockIdx.x * 32, r0 = blockIdx.y * 32;
    #pragma unroll
    for (int y = threadIdx.y; y < 32; y += 8)
        tile[y][threadIdx.x] = ib[(long)(r0 + y) * C + c0 + threadIdx.x];
    __syncthreads();
    #pragma unroll
    for (int y = threadIdx.y; y < 32; y += 8)
        ob[(long)(c0 + y) * R + r0 + threadIdx.x] = rndtf(tile[threadIdx.x][y]);
}

// ---------------- RMSNorm: two-phase reduce ----------------
// phase A: grid BB*32 blocks, each reduces 8192 elements (2048 float4).
__global__ void rms_part_k(const float* __restrict__ x, float* __restrict__ part) {
    int blk = blockIdx.x;
    int b = blk >> 5, c = blk & 31;
    const float4* xb = (const float4*)(x + (size_t)b * MD + (size_t)c * 8192);
    float s = 0.f;
    for (int i = threadIdx.x; i < 2048; i += 256) {
        float4 v = xb[i];
        s += v.x * v.x + v.y * v.y + v.z * v.z + v.w * v.w;
    }
    __shared__ float sm[8];
    for (int o = 16; o; o >>= 1) s += __shfl_xor_sync(0xffffffffu, s, o);
    if ((threadIdx.x & 31) == 0) sm[threadIdx.x >> 5] = s;
    __syncthreads();
    if (threadIdx.x < 8) {
        s = sm[threadIdx.x];
        for (int o = 4; o; o >>= 1) s += __shfl_xor_sync(0xffu, s, o);
        if (threadIdx.x == 0) part[blk] = s;
    }
}
// phase B: 1 block, 1024 threads; warp b reduces batch b's 32 partials.
__global__ void rms_fin_k(const float* __restrict__ part, float* __restrict__ ff) {
    int b = threadIdx.x >> 5, lane = threadIdx.x & 31;
    float s = part[b * 32 + lane];
    for (int o = 16; o; o >>= 1) s += __shfl_xor_sync(0xffffffffu, s, o);
    if (lane == 0) ff[b] = sqrtf((float)MD) * rsqrtf(s);
}

__global__ void rms_apply_k(const float* __restrict__ x, const float* __restrict__ scale,
                            const float* __restrict__ ff, float* __restrict__ y) {
    long i = (long)blockIdx.x * blockDim.x + threadIdx.x;
    if (i >= (long)BB * MD) return;
    int b  = (int)(i / MD);
    int md = (int)(i % MD);
    y[i] = rndtf(x[i] * scale[md] * ff[b]);
}

// ---------------- softmax, L=512 register-resident (warp per row) ----------------
__global__ void softmax512_k(float* __restrict__ s, long nrows, int doRound) {
    long row = (long)blockIdx.x * (blockDim.x >> 5) + (threadIdx.x >> 5);
    if (row >= nrows) return;
    int lane = threadIdx.x & 31;
    float4* rp = reinterpret_cast<float4*>(s + row * 512);
    float4 d[4];
    #pragma unroll
    for (int j = 0; j < 4; j++) d[j] = rp[lane + 32 * j];
    float mx = -INFINITY;
    #pragma unroll
    for (int j = 0; j < 4; j++)
        mx = fmaxf(mx, fmaxf(fmaxf(d[j].x, d[j].y), fmaxf(d[j].z, d[j].w)));
    for (int o = 16; o; o >>= 1) mx = fmaxf(mx, __shfl_xor_sync(0xffffffffu, mx, o));
    float sum = 0.f;
    #pragma unroll
    for (int j = 0; j < 4; j++) {
        d[j].x = __expf(d[j].x - mx); d[j].y = __expf(d[j].y - mx);
        d[j].z = __expf(d[j].z - mx); d[j].w = __expf(d[j].w - mx);
        sum += d[j].x + d[j].y + d[j].z + d[j].w;
    }
    for (int o = 16; o; o >>= 1) sum += __shfl_xor_sync(0xffffffffu, sum, o);
    float inv = 1.f / sum;
    #pragma unroll
    for (int j = 0; j < 4; j++) {
        float v0 = d[j].x * inv, v1 = d[j].y * inv, v2 = d[j].z * inv, v3 = d[j].w * inv;
        if (doRound) { v0 = rndtf(v0); v1 = rndtf(v1); v2 = rndtf(v2); v3 = rndtf(v3); }
        rp[lane + 32 * j] = make_float4(v0, v1, v2, v3);
    }
}

// ---------------- generic row softmax (stage-2, L=64) ----------------
__global__ void softmax_k(float* __restrict__ s, int L, long nrows, int doRound) {
    long warp = (long)blockIdx.x * (blockDim.x >> 5) + (threadIdx.x >> 5);
    if (warp >= nrows) return;
    int lane = threadIdx.x & 31;
    float* row = s + warp * (long)L;
    float mx = -INFINITY;
    for (int i = lane; i < L; i += 32) mx = fmaxf(mx, row[i]);
    for (int o = 16; o; o >>= 1) mx = fmaxf(mx, __shfl_xor_sync(0xffffffffu, mx, o));
    float sum = 0.f;
    for (int i = lane; i < L; i += 32) {
        float e = __expf(row[i] - mx);
        row[i] = e;
        sum += e;
    }
    for (int o = 16; o; o >>= 1) sum += __shfl_xor_sync(0xffffffffu, sum, o);
    float inv = 1.f / sum;
    for (int i = lane; i < L; i += 32) {
        float vv = row[i] * inv;
        row[i] = doRound ? rndtf(vv) : vv;
    }
}

// ==================== tf32 mma.sync GEMM, cp.async 3-stage ====================
// Inputs already tf32-rounded fp32 bit patterns.
// C = alpha*A@op(B) (+R)(+bias), optional fused RoPE, optional round.
// A row-major [m][k]; B: TRANSB ? [n][k] (n-major smem + ldmatrix)
//                        : [k][n] (k-major smem pitch 136 + direct LDS fragments).
// 128x128x32 CTA tile, 256 thr (2m x 4n warps), warp 64x32. M,N%128==0, K%32==0, K>=64.

#define NSTG   3
#define A_STG  4096                      // u32 per stage
#define B_STG  4352                      // u32 per stage (NN needs 32x136; TRANSB uses 4096)
#define STG_U32 (A_STG + B_STG)          // 8448
#define TG_SMEM (NSTG * STG_U32 * 4)     // 101376 bytes

template<bool TRANSB, bool RES, bool BIAS, bool ROUND, bool ROPE>
__global__ void __launch_bounds__(256, 2) tg_k(
    const float* __restrict__ A, int lda, long sAo, long sAi,
    const float* __restrict__ Bm, int ldb, long sBo, long sBi,
    float*       __restrict__ Cm, int ldc, long sCo, long sCi,
    const float* __restrict__ R, int ldr, long sRi,
    const float* __restrict__ bias,
    int K, int inner, float alpha, int angmod, float thc)
{
    extern __shared__ uint32_t smem[];

    int z  = blockIdx.z;
    int zo = z / inner;
    int zi = z - zo * inner;
    A  += zo * sAo + zi * sAi;
    Bm += zo * sBo + zi * sBi;
    Cm += zo * sCo + zi * sCi;
    if (RES) R += (long)zi * sRi;

    const int tid  = threadIdx.x;
    const int lane = tid & 31;
    const int wid  = tid >> 5;
    const int warpM = wid & 1;
    const int warpN = wid >> 1;
    const int m0 = blockIdx.y << 7;
    const int n0 = blockIdx.x << 7;

    const uint32_t sbase = cvta_smem_u32(smem);

    const int cA = tid & 7;     // 16B chunk 0..7
    const int rA = tid >> 3;    // row 0..31
    const int lr = (lane & 7) + ((lane >> 3) & 1) * 8;
    const int lc = lane >> 4;
    // NN B fragment per-thread base offset (u32 units within B stage)
    const int bfrag = (lane & 3) * 136 + warpN * 32 + (lane >> 2);

    float acc[4][4][4];
    #pragma unroll
    for (int i = 0; i < 4; i++)
        #pragma unroll
        for (int j = 0; j < 4; j++)
            #pragma unroll
            for (int r = 0; r < 4; r++) acc[i][j][r] = 0.f;

    const int niter = K >> 5;

    #define TG_ISSUE(st, k0)                                                          \
    {                                                                                 \
        uint32_t sA = sbase + (uint32_t)(st) * STG_U32 * 4;                           \
        uint32_t sB = sA + A_STG * 4;                                                 \
        _Pragma("unroll")                                                             \
        for (int g = 0; g < 4; g++) {                                                 \
            int r = rA + 32 * g;                                                      \
            int ch = cA ^ (r & 7);                                                    \
            CP16(sA + (uint32_t)(r * 32 + ch * 4) * 4,                                \
                 &A[(long)(m0 + r) * lda + (k0) + cA * 4]);                           \
            if (TRANSB) {                                                             \
                CP16(sB + (uint32_t)(r * 32 + ch * 4) * 4,                            \
                     &Bm[(long)(n0 + r) * ldb + (k0) + cA * 4]);                      \
            } else {                                                                  \
                int c = cA + 8 * g;                                                   \
                CP16(sB + (uint32_t)(rA * 136 + c * 4) * 4,                           \
                     &Bm[(long)((k0) + rA) * ldb + n0 + c * 4]);                      \
            }                                                                         \
        }                                                                             \
    }

    TG_ISSUE(0, 0);  CP_COMMIT();
    TG_ISSUE(1, 32); CP_COMMIT();

    for (int it = 0; it < niter; it++) {
        CP_WAIT1();
        __syncthreads();

        int nx = it + 2;
        if (nx < niter) { TG_ISSUE(nx % NSTG, nx << 5); }
        CP_COMMIT();   // empty group near the tail keeps wait_group<1> uniform

        int st = it % NSTG;
        const uint32_t baseA = sbase + (uint32_t)st * STG_U32 * 4;
        const uint32_t baseB = baseA + A_STG * 4;
        #pragma unroll
        for (int s = 0; s < 4; s++) {
            uint32_t af[4][4];
            #pragma unroll
            for (int i = 0; i < 4; i++) {
                int row = warpM * 64 + i * 16 + lr;
                int ch  = (2 * s + lc) ^ (row & 7);
                ldsm4(af[i], baseA + (uint32_t)(row * 32 + ch * 4) * 4);
            }
            if (TRANSB) {
                uint32_t bq[2][4];
                #pragma unroll
                for (int p = 0; p < 2; p++) {
                    int row = warpN * 32 + p * 16 + lr;
                    int ch  = (2 * s + lc) ^ (row & 7);
                    ldsm4(bq[p], baseB + (uint32_t)(row * 32 + ch * 4) * 4);
                }
                #pragma unroll
                for (int i = 0; i < 4; i++)
                    #pragma unroll
                    for (int j = 0; j < 4; j++)
                        mma_tf32(acc[i][j], af[i], bq[j >> 1][j & 1], bq[j >> 1][2 + (j & 1)]);
            } else {
                uint32_t b0[4], b1[4];
                #pragma unroll
                for (int j = 0; j < 4; j++) {
                    uint32_t ad = baseB + (uint32_t)(s * 8 * 136 + bfrag + j * 8) * 4;
                    b0[j] = lds32(ad);
                    b1[j] = lds32(ad + 544 * 4);   // +4 k-rows * pitch 136
                }
                #pragma unroll
                for (int i = 0; i < 4; i++)
                    #pragma unroll
                    for (int j = 0; j < 4; j++)
                        mma_tf32(acc[i][j], af[i], b0[j], b1[j]);
            }
        }
    }
    #undef TG_ISSUE

    // --- epilogue: alpha, (RoPE), (residual/bias), (round), store ---
    const int g8 = lane >> 2;
    const int t4 = lane & 3;
    #pragma unroll
    for (int i = 0; i < 4; i++) {
        int mrow = m0 + warpM * 64 + i * 16 + g8;
        #pragma unroll
        for (int j = 0; j < 4; j++) {
            int col = n0 + warpN * 32 + j * 8 + 2 * t4;   // always even
            float v0 = acc[i][j][0] * alpha;
            float v1 = acc[i][j][1] * alpha;
            float v2 = acc[i][j][2] * alpha;
            float v3 = acc[i][j][3] * alpha;
            if (ROPE) {
                int pair = col >> 1;
                float theta = exp2f(thc * ((float)pair - 1.0f));
                float sn0, cs0, sn1, cs1;
                sincosf((float)(mrow % angmod) * theta, &sn0, &cs0);
                sincosf((float)((mrow + 8) % angmod) * theta, &sn1, &cs1);
                float e = v0, o = v1;
                v0 = fmaf(e, cs0, o * sn0);
                v1 = fmaf(-e, sn0, o * cs0);
                e = v2; o = v3;
                v2 = fmaf(e, cs1, o * sn1);
                v3 = fmaf(-e, sn1, o * cs1);
            }
            if (RES) {
                v0 += R[(long)mrow * ldr + col];
                v1 += R[(long)mrow * ldr + col + 1];
                v2 += R[(long)(mrow + 8) * ldr + col];
                v3 += R[(long)(mrow + 8) * ldr + col + 1];
            }
            if (BIAS) {
                v0 += bias[col]; v1 += bias[col + 1];
                v2 += bias[col]; v3 += bias[col + 1];
            }
            if (ROUND) { v0 = rndtf(v0); v1 = rndtf(v1); v2 = rndtf(v2); v3 = rndtf(v3); }
            *reinterpret_cast<float2*>(&Cm[(long)mrow * ldc + col])       = make_float2(v0, v1);
            *reinterpret_cast<float2*>(&Cm[(long)(mrow + 8) * ldc + col]) = make_float2(v2, v3);
        }
    }
}

// ================= small fp32 SGEMM: 64x64 tile (stage-2 attn) =====
template<bool TRANSB, bool RES, bool BIAS>
__global__ void __launch_bounds__(256) sgemm_k(
    const float* __restrict__ A, int lda, long sAo, long sAi,
    const float* __restrict__ Bm, int ldb, long sBo, long sBi,
    float*       __restrict__ Cm, int ldc, long sCo, long sCi,
    const float* __restrict__ R, int ldr, long sRi,
    const float* __restrict__ bias,
    int K, int inner, float alpha)
{
    int z  = blockIdx.z;
    int zo = z / inner;
    int zi = z - zo * inner;
    A  += zo * sAo + zi * sAi;
    Bm += zo * sBo + zi * sBi;
    Cm += zo * sCo + zi * sCi;
    if (RES) R += (long)zi * sRi;

    __shared__ __align__(16) float As[16][68];
    __shared__ __align__(16) float Bs[16][68];

    const int tid = threadIdx.x;
    const int m0 = blockIdx.y << 6;
    const int n0 = blockIdx.x << 6;
    const int tx = tid & 15, ty = tid >> 4;

    const int ar = tid >> 2;
    const int ac = (tid & 3) << 2;
    const int br = tid >> 4;
    const int bc = (tid & 15) << 2;

    float acc[4][4] = {};

    for (int k0 = 0; k0 < K; k0 += 16) {
        float4 av = *reinterpret_cast<const float4*>(&A[(long)(m0 + ar) * lda + k0 + ac]);
        As[ac + 0][ar] = av.x; As[ac + 1][ar] = av.y;
        As[ac + 2][ar] = av.z; As[ac + 3][ar] = av.w;
        if (!TRANSB) {
            float4 bv = *reinterpret_cast<const float4*>(&Bm[(long)(k0 + br) * ldb + n0 + bc]);
            *reinterpret_cast<float4*>(&Bs[br][bc]) = bv;
        } else {
            float4 bv = *reinterpret_cast<const float4*>(&Bm[(long)(n0 + ar) * ldb + k0 + ac]);
            Bs[ac + 0][ar] = bv.x; Bs[ac + 1][ar] = bv.y;
            Bs[ac + 2][ar] = bv.z; Bs[ac + 3][ar] = bv.w;
        }
        __syncthreads();
        #pragma unroll
        for (int k = 0; k < 16; k++) {
            float4 a4 = *reinterpret_cast<const float4*>(&As[k][ty << 2]);
            float4 b4 = *reinterpret_cast<const float4*>(&Bs[k][tx << 2]);
            float a[4] = {a4.x, a4.y, a4.z, a4.w};
            float b[4] = {b4.x, b4.y, b4.z, b4.w};
            #pragma unroll
            for (int i = 0; i < 4; i++)
                #pragma unroll
                for (int j = 0; j < 4; j++)
                    acc[i][j] = fmaf(a[i], b[j], acc[i][j]);
        }
        __syncthreads();
    }

    #pragma unroll
    for (int i = 0; i < 4; i++) {
        int m = m0 + (ty << 2) + i;
        #pragma unroll
        for (int j = 0; j < 4; j++) {
            int n = n0 + (tx << 2) + j;
            float v = acc[i][j] * alpha;
            if (RES)  v += R[(long)m * ldr + n];
            if (BIAS) v += bias[n];
            Cm[(long)m * ldc + n] = v;
        }
    }
}

// ---------------- stage-2 split-K reduce ----------------
__global__ void s2red_k(const float* __restrict__ p, float* __restrict__ o) {
    long i = (long)blockIdx.x * blockDim.x + threadIdx.x;
    if (i >= (long)BB * CC * CC) return;
    float s = 0.f;
    #pragma unroll
    for (int ks = 0; ks < 8; ks++) s += p[(long)ks * BB * CC * CC + i];
    o[i] = s;
}

// ---------------- launch ----------------
extern "C" void kernel_launch(void* const* d_in, const int* in_sizes, int n_in,
                              void* d_out, int out_size) {
    const float* x     = (const float*)d_in[0];
    const float* scale = (const float*)d_in[1];
    const float* wq    = (const float*)d_in[2];
    const float* wk    = (const float*)d_in[3];
    const float* wv    = (const float*)d_in[4];
    const float* lin_w = (const float*)d_in[5];
    const float* lin_b = (const float*)d_in[6];
    const float* twq   = (const float*)d_in[7];
    const float* twk   = (const float*)d_in[8];
    const float* twv   = (const float*)d_in[9];
    float* out = (float*)d_out;

    float *x1, *q, *k, *v, *s, *cat, *x2, *x3, *t, *tq, *tk, *tv, *s2, *s2p, *t2, *ff, *red;
    float *rwqT, *rwkT, *rwvT, *rlwT, *rtwqT, *rtwkT, *rtwvT;
    cudaGetSymbolAddress((void**)&x1,  g_x1);
    cudaGetSymbolAddress((void**)&q,   g_q);
    cudaGetSymbolAddress((void**)&k,   g_k);
    cudaGetSymbolAddress((void**)&v,   g_v);
    cudaGetSymbolAddress((void**)&s,   g_s);
    cudaGetSymbolAddress((void**)&cat, g_cat);
    cudaGetSymbolAddress((void**)&x2,  g_x2);
    cudaGetSymbolAddress((void**)&x3,  g_x3);
    cudaGetSymbolAddress((void**)&t,   g_t);
    cudaGetSymbolAddress((void**)&tq,  g_tq);
    cudaGetSymbolAddress((void**)&tk,  g_tk);
    cudaGetSymbolAddress((void**)&tv,  g_tv);
    cudaGetSymbolAddress((void**)&s2,  g_s2);
    cudaGetSymbolAddress((void**)&s2p, g_s2p);
    cudaGetSymbolAddress((void**)&t2,  g_t2);
    cudaGetSymbolAddress((void**)&ff,  g_ff);
    cudaGetSymbolAddress((void**)&red, g_red);
    cudaGetSymbolAddress((void**)&rwqT, g_rwqT);
    cudaGetSymbolAddress((void**)&rwkT, g_rwkT);
    cudaGetSymbolAddress((void**)&rwvT, g_rwvT);
    cudaGetSymbolAddress((void**)&rlwT, g_rlwT);
    cudaGetSymbolAddress((void**)&rtwqT, g_rtwqT);
    cudaGetSymbolAddress((void**)&rtwkT, g_rtwkT);
    cudaGetSymbolAddress((void**)&rtwvT, g_rtwvT);

    cudaFuncSetAttribute(tg_k<true ,false,false,true ,true >, cudaFuncAttributeMaxDynamicSharedMemorySize, TG_SMEM);
    cudaFuncSetAttribute(tg_k<true ,false,false,true ,false>, cudaFuncAttributeMaxDynamicSharedMemorySize, TG_SMEM);
    cudaFuncSetAttribute(tg_k<true ,false,false,false,false>, cudaFuncAttributeMaxDynamicSharedMemorySize, TG_SMEM);
    cudaFuncSetAttribute(tg_k<true ,false,false,false,true >, cudaFuncAttributeMaxDynamicSharedMemorySize, TG_SMEM);
    cudaFuncSetAttribute(tg_k<true ,true ,true ,false,false>, cudaFuncAttributeMaxDynamicSharedMemorySize, TG_SMEM);
    cudaFuncSetAttribute(tg_k<false,false,false,true ,false>, cudaFuncAttributeMaxDynamicSharedMemorySize, TG_SMEM);

    const float th1 = -2.0f * log2f(10000.0f) / (float)DD;
    const float th2 = -2.0f * log2f(10000.0f) / (float)TDD;
    const float al1 = 1.0f / sqrtf((float)DD);
    const float al2 = 1.0f / sqrtf((float)TDD);

    // ---- weight round+transpose (B operands become [n][k]) ----
    {
        dim3 b32(32, 8);
        tpose3_k<<<dim3(DD/32, DD/32, 3*HH), b32>>>(wq, wk, wv, rwqT, rwkT, rwvT,
                                                    DD, DD, (long)DD*DD, HH);
        tpose_k<<<dim3(DD/32, (HH*DD)/32, 1), b32>>>(lin_w, rlwT, HH*DD, DD, 0, 0, 1);
        tpose3_k<<<dim3(TDD/32, TDD/32, 3), b32>>>(twq, twk, twv, rtwqT, rtwkT, rtwvT,
                                                   TDD, TDD, 0, 1);
    }

    // ---- x1 = rmsnorm(x) (tf32-rounded), 2-phase reduce ----
    rms_part_k<<<BB * 32, 256>>>(x, red);
    rms_fin_k<<<1, 1024>>>(red, ff);
    rms_apply_k<<<(BB * MD) / 256, 256>>>(x, scale, ff, x1);

    // 2) q/k/v[h,b] = x1[b] @ wT[h]^T   (q,k with fused RoPE; all rounded)
    {
        dim3 g(DD / 128, MM / 128, HH * BB);
        tg_k<true,false,false,true,true ><<<g, 256, TG_SMEM>>>(x1, DD, 0, MD, rwqT, DD, (long)DD*DD, 0,
                                                               q, DD, (long)BB * MD, MD,
                                                               nullptr, 0, 0, nullptr, DD, BB, 1.f, MM, th1);
        tg_k<true,false,false,true,true ><<<g, 256, TG_SMEM>>>(x1, DD, 0, MD, rwkT, DD, (long)DD*DD, 0,
                                                               k, DD, (long)BB * MD, MD,
                                                               nullptr, 0, 0, nullptr, DD, BB, 1.f, MM, th1);
        tg_k<true,false,false,true,false><<<g, 256, TG_SMEM>>>(x1, DD, 0, MD, rwvT, DD, (long)DD*DD, 0,
                                                               v, DD, (long)BB * MD, MD,
                                                               nullptr, 0, 0, nullptr, DD, BB, 1.f, 1, 0.f);
    }

    // 4) S = (q@k^T)/sqrt(D); softmax (reg-resident, rounded); O = P @ v (NN, rounded, cat layout)
    {
        dim3 g(MM / 128, MM / 128, HH * BB);
        tg_k<true,false,false,false,false><<<g, 256, TG_SMEM>>>(q, DD, (long)BB * MD, MD,
                                                                k, DD, (long)BB * MD, MD,
                                                                s, MM, (long)BB * MM * MM, (long)MM * MM,
                                                                nullptr, 0, 0, nullptr, DD, BB, al1, 1, 0.f);
        long nrows = (long)HH * BB * MM;
        softmax512_k<<<(int)(nrows / 8), 256>>>(s, nrows, 1);
        dim3 g2(DD / 128, MM / 128, HH * BB);
        tg_k<false,false,false,true,false><<<g2, 256, TG_SMEM>>>(s, MM, (long)BB * MM * MM, (long)MM * MM,
                                                                 v, DD, (long)BB * MD, MD,
                                                                 cat, HH * DD, (long)DD, (long)MM * HH * DD,
                                                                 nullptr, 0, 0, nullptr, MM, BB, 1.f, 1, 0.f);
    }

    // 5) x2 = x1 + cat @ rlwT^T + lin_b   (no round; feeds rmsnorm only)
    {
        dim3 g(DD / 128, (BB * MM) / 128, 1);
        tg_k<true,true,true,false,false><<<g, 256, TG_SMEM>>>(cat, HH * DD, 0, 0, rlwT, HH * DD, 0, 0,
                                                              x2, DD, 0, 0,
                                                              x1, DD, 0, lin_b, HH * DD, 1, 1.f, 1, 0.f);
    }

    // 6) x3 = rmsnorm(x2)  (rounded), 2-phase reduce
    rms_part_k<<<BB * 32, 256>>>(x2, red);
    rms_fin_k<<<1, 1024>>>(red, ff);
    rms_apply_k<<<(BB * MD) / 256, 256>>>(x2, scale, ff, x3);

    // 7) t = per-batch 512x512 transpose of x3  (channel shuffle == plain transpose)
    tpose_k<<<dim3(DD/32, MM/32, BB), dim3(32,8)>>>(x3, t, MM, DD, (long)MD, (long)MD, 0);

    // 8) tq/tk/tv = t @ rtwT^T  (tq,tk with fused stage-2 RoPE; no round, feed fp32 stage-2)
    {
        dim3 g(TDD / 128, (BB * CC) / 128, 1);
        tg_k<true,false,false,false,true ><<<g, 256, TG_SMEM>>>(t, TDD, 0, 0, rtwqT, TDD, 0, 0, tq, TDD, 0, 0,
                                                                nullptr, 0, 0, nullptr, TDD, 1, 1.f, CC, th2);
        tg_k<true,false,false,false,true ><<<g, 256, TG_SMEM>>>(t, TDD, 0, 0, rtwkT, TDD, 0, 0, tk, TDD, 0, 0,
                                                                nullptr, 0, 0, nullptr, TDD, 1, 1.f, CC, th2);
        tg_k<true,false,false,false,false><<<g, 256, TG_SMEM>>>(t, TDD, 0, 0, rtwvT, TDD, 0, 0, tv, TDD, 0, 0,
                                                                nullptr, 0, 0, nullptr, TDD, 1, 1.f, 1, 0.f);
    }

    // 10) S2 = (tq @ tk^T)/64 via split-K 8; reduce; softmax; t2 = t + P2 @ tv
    {
        dim3 g(1, 1, 8 * BB);       // zo = K-split index, zi = batch
        sgemm_k<true,false,false><<<g, 256>>>(tq, TDD, 512, (long)CC * TDD,
                                              tk, TDD, 512, (long)CC * TDD,
                                              s2p, CC, (long)BB * CC * CC, (long)CC * CC,
                                              nullptr, 0, 0, nullptr, 512, BB, al2);
        s2red_k<<<(BB * CC * CC + 255) / 256, 256>>>(s2p, s2);
        softmax_k<<<(BB * CC) / 8, 256>>>(s2, CC, (long)BB * CC, 0);
        dim3 g2(TDD / 64, 1, BB);
        sgemm_k<false,true,false><<<g2, 256>>>(s2, CC, 0, (long)CC * CC,
                                               tv, TDD, 0, (long)CC * TDD,
                                               t2, TDD, 0, (long)CC * TDD,
                                               t, TDD, (long)CC * TDD, nullptr,
                                               CC, BB, 1.f);
    }

    // 11) out = per-batch transpose of t2 back to [m][d]
    tpose_k<<<dim3(MM/32, DD/32, BB), dim3(32,8)>>>(t2, out, DD, MM, (long)MD, (long)MD, 0);
}

// round 15
// speedup vs baseline: 1.0185x; 1.0007x over previous
#include <cuda_runtime.h>
#include <math.h>
#include <stdint.h>

// ---------------- problem constants ----------------
#define BB 32
#define MM 512
#define DD 512
#define HH 8
#define FF 8
#define CC 64           // DD / FF
#define TDD 4096        // FF * MM
#define MD (MM * DD)    // 262144

// ---------------- device scratch (no allocs allowed) ----------------
__device__ float g_x1 [(size_t)BB * MD];
__device__ float g_q  [(size_t)HH * BB * MD];
__device__ float g_k  [(size_t)HH * BB * MD];
__device__ float g_v  [(size_t)HH * BB * MD];
__device__ float g_s  [(size_t)HH * BB * MM * MM];
__device__ float g_cat[(size_t)BB * MM * HH * DD];
__device__ float g_x2 [(size_t)BB * MD];
__device__ float g_x3 [(size_t)BB * MD];
__device__ float g_t  [(size_t)BB * CC * TDD];
__device__ float g_tq [(size_t)BB * CC * TDD];
__device__ float g_tk [(size_t)BB * CC * TDD];
__device__ float g_tv [(size_t)BB * CC * TDD];
__device__ float g_s2 [(size_t)BB * CC * CC];
__device__ float g_s2p[(size_t)8 * BB * CC * CC];
__device__ float g_t2 [(size_t)BB * CC * TDD];
__device__ float g_ff [BB];
__device__ float g_red[BB * 32];
// tf32-rounded, TRANSPOSED weight copies (B operands, [n][k] layout)
__device__ float g_rwqT[(size_t)HH * DD * DD];
__device__ float g_rwkT[(size_t)HH * DD * DD];
__device__ float g_rwvT[(size_t)HH * DD * DD];
__device__ float g_rlwT[(size_t)HH * DD * DD];      // [512][4096]
__device__ float g_rtwqT[(size_t)TDD * TDD];
__device__ float g_rtwkT[(size_t)TDD * TDD];
__device__ float g_rtwvT[(size_t)TDD * TDD];

// ---------------- tf32 helpers ----------------
__device__ __forceinline__ uint32_t f2tf(float f) {
    uint32_t r;
    asm("cvt.rna.tf32.f32 %0, %1;" : "=r"(r) : "f"(f));
    return r;
}
__device__ __forceinline__ float rndtf(float f) { return __uint_as_float(f2tf(f)); }

__device__ __forceinline__ uint32_t cvta_smem_u32(const void* p) {
    uint32_t r;
    asm("{ .reg .u64 t; cvta.to.shared.u64 t, %1; cvt.u32.u64 %0, t; }" : "=r"(r) : "l"(p));
    return r;
}
__device__ __forceinline__ void ldsm4(uint32_t r[4], uint32_t addr) {
    asm volatile("ldmatrix.sync.aligned.m8n8.x4.shared.b16 {%0,%1,%2,%3}, [%4];"
                 : "=r"(r[0]), "=r"(r[1]), "=r"(r[2]), "=r"(r[3]) : "r"(addr));
}
__device__ __forceinline__ uint32_t lds32(uint32_t addr) {
    uint32_t v;
    asm volatile("ld.shared.b32 %0, [%1];" : "=r"(v) : "r"(addr));
    return v;
}
__device__ __forceinline__ void mma_tf32(float c[4], const uint32_t a[4], uint32_t b0, uint32_t b1) {
    asm volatile("mma.sync.aligned.m16n8k8.row.col.f32.tf32.tf32.f32 "
                 "{%0,%1,%2,%3}, {%4,%5,%6,%7}, {%8,%9}, {%0,%1,%2,%3};"
                 : "+f"(c[0]), "+f"(c[1]), "+f"(c[2]), "+f"(c[3])
                 : "r"(a[0]), "r"(a[1]), "r"(a[2]), "r"(a[3]), "r"(b0), "r"(b1));
}
#define CP16(dst, src) asm volatile("cp.async.cg.shared.global [%0], [%1], 16;" :: "r"(dst), "l"(src))
#define CP_COMMIT()    asm volatile("cp.async.commit_group;")
#define CP_WAIT1()     asm volatile("cp.async.wait_group 1;")

// ---------------- tiled transpose (+optional tf32 round): out[c][r] = in[r][c] ----------------
// block (32,8), grid (C/32, R/32, batch). R,C multiples of 32.
__global__ void tpose_k(const float* __restrict__ in, float* __restrict__ out,
                        int R, int C, long sIn, long sOut, int doRound) {
    __shared__ float tile[32][33];
    const float* ib = in  + (long)blockIdx.z * sIn;
    float*       ob = out + (long)blockIdx.z * sOut;
    int c0 = blockIdx.x * 32, r0 = blockIdx.y * 32;
    #pragma unroll
    for (int y = threadIdx.y; y < 32; y += 8)
        tile[y][threadIdx.x] = ib[(long)(r0 + y) * C + c0 + threadIdx.x];
    __syncthreads();
    #pragma unroll
    for (int y = threadIdx.y; y < 32; y += 8) {
        float v = tile[threadIdx.x][y];
        ob[(long)(c0 + y) * R + r0 + threadIdx.x] = doRound ? rndtf(v) : v;
    }
}

// transpose 3 weight sets in one launch (always rounds). grid (C/32, R/32, 3*nb).
__global__ void tpose3_k(const float* __restrict__ i0, const float* __restrict__ i1,
                         const float* __restrict__ i2,
                         float* __restrict__ o0, float* __restrict__ o1, float* __restrict__ o2,
                         int R, int C, long stride, int nb) {
    __shared__ float tile[32][33];
    int z = blockIdx.z;
    int sel = z / nb, bb = z % nb;
    const float* in  = (sel == 0) ? i0 : (sel == 1) ? i1 : i2;
    float*       out = (sel == 0) ? o0 : (sel == 1) ? o1 : o2;
    const float* ib = in  + (long)bb * stride;
    float*       ob = out + (long)bb * stride;
    int c0 = blockIdx.x * 32, r0 = blockIdx.y * 32;
    #pragma unroll
    for (int y = threadIdx.y; y < 32; y += 8)
        tile[y][threadIdx.x] = ib[(long)(r0 + y) * C + c0 + threadIdx.x];
    __syncthreads();
    #pragma unroll
    for (int y = threadIdx.y; y < 32; y += 8)
        ob[(long)(c0 + y) * R + r0 + threadIdx.x] = rndtf(tile[threadIdx.x][y]);
}

// ---------------- RMSNorm: two-phase reduce ----------------
// phase A: grid BB*32 blocks, each reduces 8192 elements (2048 float4).
__global__ void rms_part_k(const float* __restrict__ x, float* __restrict__ part) {
    int blk = blockIdx.x;
    int b = blk >> 5, c = blk & 31;
    const float4* xb = (const float4*)(x + (size_t)b * MD + (size_t)c * 8192);
    float s = 0.f;
    for (int i = threadIdx.x; i < 2048; i += 256) {
        float4 v = xb[i];
        s += v.x * v.x + v.y * v.y + v.z * v.z + v.w * v.w;
    }
    __shared__ float sm[8];
    for (int o = 16; o; o >>= 1) s += __shfl_xor_sync(0xffffffffu, s, o);
    if ((threadIdx.x & 31) == 0) sm[threadIdx.x >> 5] = s;
    __syncthreads();
    if (threadIdx.x < 8) {
        s = sm[threadIdx.x];
        for (int o = 4; o; o >>= 1) s += __shfl_xor_sync(0xffu, s, o);
        if (threadIdx.x == 0) part[blk] = s;
    }
}
// phase B: 1 block, 1024 threads; warp b reduces batch b's 32 partials.
__global__ void rms_fin_k(const float* __restrict__ part, float* __restrict__ ff) {
    int b = threadIdx.x >> 5, lane = threadIdx.x & 31;
    float s = part[b * 32 + lane];
    for (int o = 16; o; o >>= 1) s += __shfl_xor_sync(0xffffffffu, s, o);
    if (lane == 0) ff[b] = sqrtf((float)MD) * rsqrtf(s);
}

__global__ void rms_apply_k(const float* __restrict__ x, const float* __restrict__ scale,
                            const float* __restrict__ ff, float* __restrict__ y) {
    long i = (long)blockIdx.x * blockDim.x + threadIdx.x;
    if (i >= (long)BB * MD) return;
    int b  = (int)(i / MD);
    int md = (int)(i % MD);
    y[i] = rndtf(x[i] * scale[md] * ff[b]);
}

// ---------------- softmax, L=512 register-resident (warp per row) ----------------
__global__ void softmax512_k(float* __restrict__ s, long nrows, int doRound) {
    long row = (long)blockIdx.x * (blockDim.x >> 5) + (threadIdx.x >> 5);
    if (row >= nrows) return;
    int lane = threadIdx.x & 31;
    float4* rp = reinterpret_cast<float4*>(s + row * 512);
    float4 d[4];
    #pragma unroll
    for (int j = 0; j < 4; j++) d[j] = rp[lane + 32 * j];
    float mx = -INFINITY;
    #pragma unroll
    for (int j = 0; j < 4; j++)
        mx = fmaxf(mx, fmaxf(fmaxf(d[j].x, d[j].y), fmaxf(d[j].z, d[j].w)));
    for (int o = 16; o; o >>= 1) mx = fmaxf(mx, __shfl_xor_sync(0xffffffffu, mx, o));
    float sum = 0.f;
    #pragma unroll
    for (int j = 0; j < 4; j++) {
        d[j].x = __expf(d[j].x - mx); d[j].y = __expf(d[j].y - mx);
        d[j].z = __expf(d[j].z - mx); d[j].w = __expf(d[j].w - mx);
        sum += d[j].x + d[j].y + d[j].z + d[j].w;
    }
    for (int o = 16; o; o >>= 1) sum += __shfl_xor_sync(0xffffffffu, sum, o);
    float inv = 1.f / sum;
    #pragma unroll
    for (int j = 0; j < 4; j++) {
        float v0 = d[j].x * inv, v1 = d[j].y * inv, v2 = d[j].z * inv, v3 = d[j].w * inv;
        if (doRound) { v0 = rndtf(v0); v1 = rndtf(v1); v2 = rndtf(v2); v3 = rndtf(v3); }
        rp[lane + 32 * j] = make_float4(v0, v1, v2, v3);
    }
}

// ---------------- generic row softmax (stage-2, L=64) ----------------
__global__ void softmax_k(float* __restrict__ s, int L, long nrows, int doRound) {
    long warp = (long)blockIdx.x * (blockDim.x >> 5) + (threadIdx.x >> 5);
    if (warp >= nrows) return;
    int lane = threadIdx.x & 31;
    float* row = s + warp * (long)L;
    float mx = -INFINITY;
    for (int i = lane; i < L; i += 32) mx = fmaxf(mx, row[i]);
    for (int o = 16; o; o >>= 1) mx = fmaxf(mx, __shfl_xor_sync(0xffffffffu, mx, o));
    float sum = 0.f;
    for (int i = lane; i < L; i += 32) {
        float e = __expf(row[i] - mx);
        row[i] = e;
        sum += e;
    }
    for (int o = 16; o; o >>= 1) sum += __shfl_xor_sync(0xffffffffu, sum, o);
    float inv = 1.f / sum;
    for (int i = lane; i < L; i += 32) {
        float vv = row[i] * inv;
        row[i] = doRound ? rndtf(vv) : vv;
    }
}

// ==================== tf32 mma.sync GEMM, cp.async 3-stage ====================
// Inputs already tf32-rounded fp32 bit patterns.
// C = alpha*A@op(B) (+R)(+bias), optional fused RoPE, optional round.
// A row-major [m][k]; B: TRANSB ? [n][k] (n-major smem + ldmatrix)
//                        : [k][n] (k-major smem pitch 136 + direct LDS fragments).
// 128x128x32 CTA tile, 256 thr (2m x 4n warps), warp 64x32. M,N%128==0, K%32==0, K>=64.

#define NSTG   3
#define A_STG  4096                      // u32 per stage
#define B_STG  4352                      // u32 per stage (NN needs 32x136; TRANSB uses 4096)
#define STG_U32 (A_STG + B_STG)          // 8448
#define TG_SMEM (NSTG * STG_U32 * 4)     // 101376 bytes

template<bool TRANSB, bool RES, bool BIAS, bool ROUND, bool ROPE>
__global__ void __launch_bounds__(256, 2) tg_k(
    const float* __restrict__ A, int lda, long sAo, long sAi,
    const float* __restrict__ Bm, int ldb, long sBo, long sBi,
    float*       __restrict__ Cm, int ldc, long sCo, long sCi,
    const float* __restrict__ R, int ldr, long sRi,
    const float* __restrict__ bias,
    int K, int inner, float alpha, int angmod, float thc)
{
    extern __shared__ uint32_t smem[];

    int z  = blockIdx.z;
    int zo = z / inner;
    int zi = z - zo * inner;
    A  += zo * sAo + zi * sAi;
    Bm += zo * sBo + zi * sBi;
    Cm += zo * sCo + zi * sCi;
    if (RES) R += (long)zi * sRi;

    const int tid  = threadIdx.x;
    const int lane = tid & 31;
    const int wid  = tid >> 5;
    const int warpM = wid & 1;
    const int warpN = wid >> 1;
    const int m0 = blockIdx.y << 7;
    const int n0 = blockIdx.x << 7;

    const uint32_t sbase = cvta_smem_u32(smem);

    const int cA = tid & 7;     // 16B chunk 0..7
    const int rA = tid >> 3;    // row 0..31
    const int lr = (lane & 7) + ((lane >> 3) & 1) * 8;
    const int lc = lane >> 4;
    // NN B fragment per-thread base offset (u32 units within B stage)
    const int bfrag = (lane & 3) * 136 + warpN * 32 + (lane >> 2);

    float acc[4][4][4];
    #pragma unroll
    for (int i = 0; i < 4; i++)
        #pragma unroll
        for (int j = 0; j < 4; j++)
            #pragma unroll
            for (int r = 0; r < 4; r++) acc[i][j][r] = 0.f;

    const int niter = K >> 5;

    #define TG_ISSUE(st, k0)                                                          \
    {                                                                                 \
        uint32_t sA = sbase + (uint32_t)(st) * STG_U32 * 4;                           \
        uint32_t sB = sA + A_STG * 4;                                                 \
        _Pragma("unroll")                                                             \
        for (int g = 0; g < 4; g++) {                                                 \
            int r = rA + 32 * g;                                                      \
            int ch = cA ^ (r & 7);                                                    \
            CP16(sA + (uint32_t)(r * 32 + ch * 4) * 4,                                \
                 &A[(long)(m0 + r) * lda + (k0) + cA * 4]);                           \
            if (TRANSB) {                                                             \
                CP16(sB + (uint32_t)(r * 32 + ch * 4) * 4,                            \
                     &Bm[(long)(n0 + r) * ldb + (k0) + cA * 4]);                      \
            } else {                                                                  \
                int c = cA + 8 * g;                                                   \
                CP16(sB + (uint32_t)(rA * 136 + c * 4) * 4,                           \
                     &Bm[(long)((k0) + rA) * ldb + n0 + c * 4]);                      \
            }                                                                         \
        }                                                                             \
    }

    TG_ISSUE(0, 0);  CP_COMMIT();
    TG_ISSUE(1, 32); CP_COMMIT();

    for (int it = 0; it < niter; it++) {
        CP_WAIT1();
        __syncthreads();

        int nx = it + 2;
        if (nx < niter) { TG_ISSUE(nx % NSTG, nx << 5); }
        CP_COMMIT();   // empty group near the tail keeps wait_group<1> uniform

        int st = it % NSTG;
        const uint32_t baseA = sbase + (uint32_t)st * STG_U32 * 4;
        const uint32_t baseB = baseA + A_STG * 4;
        #pragma unroll
        for (int s = 0; s < 4; s++) {
            uint32_t af[4][4];
            #pragma unroll
            for (int i = 0; i < 4; i++) {
                int row = warpM * 64 + i * 16 + lr;
                int ch  = (2 * s + lc) ^ (row & 7);
                ldsm4(af[i], baseA + (uint32_t)(row * 32 + ch * 4) * 4);
            }
            if (TRANSB) {
                uint32_t bq[2][4];
                #pragma unroll
                for (int p = 0; p < 2; p++) {
                    int row = warpN * 32 + p * 16 + lr;
                    int ch  = (2 * s + lc) ^ (row & 7);
                    ldsm4(bq[p], baseB + (uint32_t)(row * 32 + ch * 4) * 4);
                }
                #pragma unroll
                for (int i = 0; i < 4; i++)
                    #pragma unroll
                    for (int j = 0; j < 4; j++)
                        mma_tf32(acc[i][j], af[i], bq[j >> 1][j & 1], bq[j >> 1][2 + (j & 1)]);
            } else {
                uint32_t b0[4], b1[4];
                #pragma unroll
                for (int j = 0; j < 4; j++) {
                    uint32_t ad = baseB + (uint32_t)(s * 8 * 136 + bfrag + j * 8) * 4;
                    b0[j] = lds32(ad);
                    b1[j] = lds32(ad + 544 * 4);   // +4 k-rows * pitch 136
                }
                #pragma unroll
                for (int i = 0; i < 4; i++)
                    #pragma unroll
                    for (int j = 0; j < 4; j++)
                        mma_tf32(acc[i][j], af[i], b0[j], b1[j]);
            }
        }
    }
    #undef TG_ISSUE

    // --- epilogue: alpha, (RoPE), (residual/bias), (round), store ---
    const int g8 = lane >> 2;
    const int t4 = lane & 3;
    #pragma unroll
    for (int i = 0; i < 4; i++) {
        int mrow = m0 + warpM * 64 + i * 16 + g8;
        #pragma unroll
        for (int j = 0; j < 4; j++) {
            int col = n0 + warpN * 32 + j * 8 + 2 * t4;   // always even
            float v0 = acc[i][j][0] * alpha;
            float v1 = acc[i][j][1] * alpha;
            float v2 = acc[i][j][2] * alpha;
            float v3 = acc[i][j][3] * alpha;
            if (ROPE) {
                int pair = col >> 1;
                float theta = exp2f(thc * ((float)pair - 1.0f));
                float sn0, cs0, sn1, cs1;
                sincosf((float)(mrow % angmod) * theta, &sn0, &cs0);
                sincosf((float)((mrow + 8) % angmod) * theta, &sn1, &cs1);
                float e = v0, o = v1;
                v0 = fmaf(e, cs0, o * sn0);
                v1 = fmaf(-e, sn0, o * cs0);
                e = v2; o = v3;
                v2 = fmaf(e, cs1, o * sn1);
                v3 = fmaf(-e, sn1, o * cs1);
            }
            if (RES) {
                v0 += R[(long)mrow * ldr + col];
                v1 += R[(long)mrow * ldr + col + 1];
                v2 += R[(long)(mrow + 8) * ldr + col];
                v3 += R[(long)(mrow + 8) * ldr + col + 1];
            }
            if (BIAS) {
                v0 += bias[col]; v1 += bias[col + 1];
                v2 += bias[col]; v3 += bias[col + 1];
            }
            if (ROUND) { v0 = rndtf(v0); v1 = rndtf(v1); v2 = rndtf(v2); v3 = rndtf(v3); }
            *reinterpret_cast<float2*>(&Cm[(long)mrow * ldc + col])       = make_float2(v0, v1);
            *reinterpret_cast<float2*>(&Cm[(long)(mrow + 8) * ldc + col]) = make_float2(v2, v3);
        }
    }
}

// ================= small fp32 SGEMM: 64x64 tile (stage-2 attn) =====
template<bool TRANSB, bool RES, bool BIAS>
__global__ void __launch_bounds__(256) sgemm_k(
    const float* __restrict__ A, int lda, long sAo, long sAi,
    const float* __restrict__ Bm, int ldb, long sBo, long sBi,
    float*       __restrict__ Cm, int ldc, long sCo, long sCi,
    const float* __restrict__ R, int ldr, long sRi,
    const float* __restrict__ bias,
    int K, int inner, float alpha)
{
    int z  = blockIdx.z;
    int zo = z / inner;
    int zi = z - zo * inner;
    A  += zo * sAo + zi * sAi;
    Bm += zo * sBo + zi * sBi;
    Cm += zo * sCo + zi * sCi;
    if (RES) R += (long)zi * sRi;

    __shared__ __align__(16) float As[16][68];
    __shared__ __align__(16) float Bs[16][68];

    const int tid = threadIdx.x;
    const int m0 = blockIdx.y << 6;
    const int n0 = blockIdx.x << 6;
    const int tx = tid & 15, ty = tid >> 4;

    const int ar = tid >> 2;
    const int ac = (tid & 3) << 2;
    const int br = tid >> 4;
    const int bc = (tid & 15) << 2;

    float acc[4][4] = {};

    for (int k0 = 0; k0 < K; k0 += 16) {
        float4 av = *reinterpret_cast<const float4*>(&A[(long)(m0 + ar) * lda + k0 + ac]);
        As[ac + 0][ar] = av.x; As[ac + 1][ar] = av.y;
        As[ac + 2][ar] = av.z; As[ac + 3][ar] = av.w;
        if (!TRANSB) {
            float4 bv = *reinterpret_cast<const float4*>(&Bm[(long)(k0 + br) * ldb + n0 + bc]);
            *reinterpret_cast<float4*>(&Bs[br][bc]) = bv;
        } else {
            float4 bv = *reinterpret_cast<const float4*>(&Bm[(long)(n0 + ar) * ldb + k0 + ac]);
            Bs[ac + 0][ar] = bv.x; Bs[ac + 1][ar] = bv.y;
            Bs[ac + 2][ar] = bv.z; Bs[ac + 3][ar] = bv.w;
        }
        __syncthreads();
        #pragma unroll
        for (int k = 0; k < 16; k++) {
            float4 a4 = *reinterpret_cast<const float4*>(&As[k][ty << 2]);
            float4 b4 = *reinterpret_cast<const float4*>(&Bs[k][tx << 2]);
            float a[4] = {a4.x, a4.y, a4.z, a4.w};
            float b[4] = {b4.x, b4.y, b4.z, b4.w};
            #pragma unroll
            for (int i = 0; i < 4; i++)
                #pragma unroll
                for (int j = 0; j < 4; j++)
                    acc[i][j] = fmaf(a[i], b[j], acc[i][j]);
        }
        __syncthreads();
    }

    #pragma unroll
    for (int i = 0; i < 4; i++) {
        int m = m0 + (ty << 2) + i;
        #pragma unroll
        for (int j = 0; j < 4; j++) {
            int n = n0 + (tx << 2) + j;
            float v = acc[i][j] * alpha;
            if (RES)  v += R[(long)m * ldr + n];
            if (BIAS) v += bias[n];
            Cm[(long)m * ldc + n] = v;
        }
    }
}

// ---------------- stage-2 split-K reduce ----------------
__global__ void s2red_k(const float* __restrict__ p, float* __restrict__ o) {
    long i = (long)blockIdx.x * blockDim.x + threadIdx.x;
    if (i >= (long)BB * CC * CC) return;
    float s = 0.f;
    #pragma unroll
    for (int ks = 0; ks < 8; ks++) s += p[(long)ks * BB * CC * CC + i];
    o[i] = s;
}

// ---------------- launch ----------------
extern "C" void kernel_launch(void* const* d_in, const int* in_sizes, int n_in,
                              void* d_out, int out_size) {
    const float* x     = (const float*)d_in[0];
    const float* scale = (const float*)d_in[1];
    const float* wq    = (const float*)d_in[2];
    const float* wk    = (const float*)d_in[3];
    const float* wv    = (const float*)d_in[4];
    const float* lin_w = (const float*)d_in[5];
    const float* lin_b = (const float*)d_in[6];
    const float* twq   = (const float*)d_in[7];
    const float* twk   = (const float*)d_in[8];
    const float* twv   = (const float*)d_in[9];
    float* out = (float*)d_out;

    float *x1, *q, *k, *v, *s, *cat, *x2, *x3, *t, *tq, *tk, *tv, *s2, *s2p, *t2, *ff, *red;
    float *rwqT, *rwkT, *rwvT, *rlwT, *rtwqT, *rtwkT, *rtwvT;
    cudaGetSymbolAddress((void**)&x1,  g_x1);
    cudaGetSymbolAddress((void**)&q,   g_q);
    cudaGetSymbolAddress((void**)&k,   g_k);
    cudaGetSymbolAddress((void**)&v,   g_v);
    cudaGetSymbolAddress((void**)&s,   g_s);
    cudaGetSymbolAddress((void**)&cat, g_cat);
    cudaGetSymbolAddress((void**)&x2,  g_x2);
    cudaGetSymbolAddress((void**)&x3,  g_x3);
    cudaGetSymbolAddress((void**)&t,   g_t);
    cudaGetSymbolAddress((void**)&tq,  g_tq);
    cudaGetSymbolAddress((void**)&tk,  g_tk);
    cudaGetSymbolAddress((void**)&tv,  g_tv);
    cudaGetSymbolAddress((void**)&s2,  g_s2);
    cudaGetSymbolAddress((void**)&s2p, g_s2p);
    cudaGetSymbolAddress((void**)&t2,  g_t2);
    cudaGetSymbolAddress((void**)&ff,  g_ff);
    cudaGetSymbolAddress((void**)&red, g_red);
    cudaGetSymbolAddress((void**)&rwqT, g_rwqT);
    cudaGetSymbolAddress((void**)&rwkT, g_rwkT);
    cudaGetSymbolAddress((void**)&rwvT, g_rwvT);
    cudaGetSymbolAddress((void**)&rlwT, g_rlwT);
    cudaGetSymbolAddress((void**)&rtwqT, g_rtwqT);
    cudaGetSymbolAddress((void**)&rtwkT, g_rtwkT);
    cudaGetSymbolAddress((void**)&rtwvT, g_rtwvT);

    cudaFuncSetAttribute(tg_k<true ,false,false,true ,true >, cudaFuncAttributeMaxDynamicSharedMemorySize, TG_SMEM);
    cudaFuncSetAttribute(tg_k<true ,false,false,true ,false>, cudaFuncAttributeMaxDynamicSharedMemorySize, TG_SMEM);
    cudaFuncSetAttribute(tg_k<true ,false,false,false,false>, cudaFuncAttributeMaxDynamicSharedMemorySize, TG_SMEM);
    cudaFuncSetAttribute(tg_k<true ,false,false,false,true >, cudaFuncAttributeMaxDynamicSharedMemorySize, TG_SMEM);
    cudaFuncSetAttribute(tg_k<true ,true ,true ,false,false>, cudaFuncAttributeMaxDynamicSharedMemorySize, TG_SMEM);
    cudaFuncSetAttribute(tg_k<false,false,false,true ,false>, cudaFuncAttributeMaxDynamicSharedMemorySize, TG_SMEM);

    const float th1 = -2.0f * log2f(10000.0f) / (float)DD;
    const float th2 = -2.0f * log2f(10000.0f) / (float)TDD;
    const float al1 = 1.0f / sqrtf((float)DD);
    const float al2 = 1.0f / sqrtf((float)TDD);

    // ---- weight round+transpose (B operands become [n][k]) ----
    {
        dim3 b32(32, 8);
        tpose3_k<<<dim3(DD/32, DD/32, 3*HH), b32>>>(wq, wk, wv, rwqT, rwkT, rwvT,
                                                    DD, DD, (long)DD*DD, HH);
        tpose_k<<<dim3(DD/32, (HH*DD)/32, 1), b32>>>(lin_w, rlwT, HH*DD, DD, 0, 0, 1);
        tpose3_k<<<dim3(TDD/32, TDD/32, 3), b32>>>(twq, twk, twv, rtwqT, rtwkT, rtwvT,
                                                   TDD, TDD, 0, 1);
    }

    // ---- x1 = rmsnorm(x) (tf32-rounded), 2-phase reduce ----
    rms_part_k<<<BB * 32, 256>>>(x, red);
    rms_fin_k<<<1, 1024>>>(red, ff);
    rms_apply_k<<<(BB * MD) / 256, 256>>>(x, scale, ff, x1);

    // 2) q/k/v[h,b] = x1[b] @ wT[h]^T   (q,k with fused RoPE; all rounded)
    {
        dim3 g(DD / 128, MM / 128, HH * BB);
        tg_k<true,false,false,true,true ><<<g, 256, TG_SMEM>>>(x1, DD, 0, MD, rwqT, DD, (long)DD*DD, 0,
                                                               q, DD, (long)BB * MD, MD,
                                                               nullptr, 0, 0, nullptr, DD, BB, 1.f, MM, th1);
        tg_k<true,false,false,true,true ><<<g, 256, TG_SMEM>>>(x1, DD, 0, MD, rwkT, DD, (long)DD*DD, 0,
                                                               k, DD, (long)BB * MD, MD,
                                                               nullptr, 0, 0, nullptr, DD, BB, 1.f, MM, th1);
        tg_k<true,false,false,true,false><<<g, 256, TG_SMEM>>>(x1, DD, 0, MD, rwvT, DD, (long)DD*DD, 0,
                                                               v, DD, (long)BB * MD, MD,
                                                               nullptr, 0, 0, nullptr, DD, BB, 1.f, 1, 0.f);
    }

    // 4) S = (q@k^T)/sqrt(D); softmax (reg-resident, rounded); O = P @ v (NN, rounded, cat layout)
    {
        dim3 g(MM / 128, MM / 128, HH * BB);
        tg_k<true,false,false,false,false><<<g, 256, TG_SMEM>>>(q, DD, (long)BB * MD, MD,
                                                                k, DD, (long)BB * MD, MD,
                                                                s, MM, (long)BB * MM * MM, (long)MM * MM,
                                                                nullptr, 0, 0, nullptr, DD, BB, al1, 1, 0.f);
        long nrows = (long)HH * BB * MM;
        softmax512_k<<<(int)(nrows / 8), 256>>>(s, nrows, 1);
        dim3 g2(DD / 128, MM / 128, HH * BB);
        tg_k<false,false,false,true,false><<<g2, 256, TG_SMEM>>>(s, MM, (long)BB * MM * MM, (long)MM * MM,
                                                                 v, DD, (long)BB * MD, MD,
                                                                 cat, HH * DD, (long)DD, (long)MM * HH * DD,
                                                                 nullptr, 0, 0, nullptr, MM, BB, 1.f, 1, 0.f);
    }

    // 5) x2 = x1 + cat @ rlwT^T + lin_b   (no round; feeds rmsnorm only)
    {
        dim3 g(DD / 128, (BB * MM) / 128, 1);
        tg_k<true,true,true,false,false><<<g, 256, TG_SMEM>>>(cat, HH * DD, 0, 0, rlwT, HH * DD, 0, 0,
                                                              x2, DD, 0, 0,
                                                              x1, DD, 0, lin_b, HH * DD, 1, 1.f, 1, 0.f);
    }

    // 6) x3 = rmsnorm(x2)  (rounded), 2-phase reduce
    rms_part_k<<<BB * 32, 256>>>(x2, red);
    rms_fin_k<<<1, 1024>>>(red, ff);
    rms_apply_k<<<(BB * MD) / 256, 256>>>(x2, scale, ff, x3);

    // 7) t = per-batch 512x512 transpose of x3  (channel shuffle == plain transpose)
    tpose_k<<<dim3(DD/32, MM/32, BB), dim3(32,8)>>>(x3, t, MM, DD, (long)MD, (long)MD, 0);

    // 8) tq/tk/tv = t @ rtwT^T  (tq,tk with fused stage-2 RoPE; no round, feed fp32 stage-2)
    {
        dim3 g(TDD / 128, (BB * CC) / 128, 1);
        tg_k<true,false,false,false,true ><<<g, 256, TG_SMEM>>>(t, TDD, 0, 0, rtwqT, TDD, 0, 0, tq, TDD, 0, 0,
                                                                nullptr, 0, 0, nullptr, TDD, 1, 1.f, CC, th2);
        tg_k<true,false,false,false,true ><<<g, 256, TG_SMEM>>>(t, TDD, 0, 0, rtwkT, TDD, 0, 0, tk, TDD, 0, 0,
                                                                nullptr, 0, 0, nullptr, TDD, 1, 1.f, CC, th2);
        tg_k<true,false,false,false,false><<<g, 256, TG_SMEM>>>(t, TDD, 0, 0, rtwvT, TDD, 0, 0, tv, TDD, 0, 0,
                                                                nullptr, 0, 0, nullptr, TDD, 1, 1.f, 1, 0.f);
    }

    // 10) S2 = (tq @ tk^T)/64 via split-K 8; reduce; softmax; t2 = t + P2 @ tv
    {
        dim3 g(1, 1, 8 * BB);       // zo = K-split index, zi = batch
        sgemm_k<true,false,false><<<g, 256>>>(tq, TDD, 512, (long)CC * TDD,
                                              tk, TDD, 512, (long)CC * TDD,
                                              s2p, CC, (long)BB * CC * CC, (long)CC * CC,
                                              nullptr, 0, 0, nullptr, 512, BB, al2);
        s2red_k<<<(BB * CC * CC + 255) / 256, 256>>>(s2p, s2);
        softmax_k<<<(BB * CC) / 8, 256>>>(s2, CC, (long)BB * CC, 0);
        dim3 g2(TDD / 64, 1, BB);
        sgemm_k<false,true,false><<<g2, 256>>>(s2, CC, 0, (long)CC * CC,
                                               tv, TDD, 0, (long)CC * TDD,
                                               t2, TDD, 0, (long)CC * TDD,
                                               t, TDD, (long)CC * TDD, nullptr,
                                               CC, BB, 1.f);
    }

    // 11) out = per-batch transpose of t2 back to [m][d]
    tpose_k<<<dim3(MM/32, DD/32, BB), dim3(32,8)>>>(t2, out, DD, MM, (long)MD, (long)MD, 0);
}

// round 16
// speedup vs baseline: 1.7491x; 1.7175x over previous
#include <cuda_runtime.h>
#include <cuda_fp16.h>
#include <math.h>
#include <stdint.h>

// ---------------- problem constants ----------------
#define BB 32
#define MM 512
#define DD 512
#define HH 8
#define FF 8
#define CC 64           // DD / FF
#define TDD 4096        // FF * MM
#define MD (MM * DD)    // 262144

// ---------------- device scratch (no allocs allowed) ----------------
__device__ __half h_x1 [(size_t)BB * MD];
__device__ __half h_q  [(size_t)HH * BB * MD];
__device__ __half h_k  [(size_t)HH * BB * MD];
__device__ __half h_vT [(size_t)HH * BB * MD];
__device__ __half h_p  [(size_t)HH * BB * MM * MM];   // P (post-softmax), fp16
__device__ __half h_cat[(size_t)BB * MM * HH * DD];
__device__ __half h_t  [(size_t)BB * CC * TDD];
__device__ float  g_s  [(size_t)HH * BB * MM * MM];   // S logits, fp32
__device__ float  g_x2 [(size_t)BB * MD];
__device__ float  g_x3 [(size_t)BB * MD];
__device__ float  g_t  [(size_t)BB * CC * TDD];       // fp32 t for residual
__device__ float  g_tq [(size_t)BB * CC * TDD];
__device__ float  g_tk [(size_t)BB * CC * TDD];
__device__ float  g_tv [(size_t)BB * CC * TDD];
__device__ float  g_s2 [(size_t)BB * CC * CC];
__device__ float  g_s2p[(size_t)8 * BB * CC * CC];
__device__ float  g_t2 [(size_t)BB * CC * TDD];
__device__ float  g_ff [BB];
__device__ float  g_red[BB * 32];
// fp16, TRANSPOSED weight copies (B operands, [n][k] layout)
__device__ __half h_rwqT[(size_t)HH * DD * DD];
__device__ __half h_rwkT[(size_t)HH * DD * DD];
__device__ __half h_rwvT[(size_t)HH * DD * DD];
__device__ __half h_rlwT[(size_t)HH * DD * DD];      // [512][4096]
__device__ __half h_rtwqT[(size_t)TDD * TDD];
__device__ __half h_rtwkT[(size_t)TDD * TDD];
__device__ __half h_rtwvT[(size_t)TDD * TDD];

// ---------------- helpers ----------------
__device__ __forceinline__ uint32_t cvta_smem_u32(const void* p) {
    uint32_t r;
    asm("{ .reg .u64 t; cvta.to.shared.u64 t, %1; cvt.u32.u64 %0, t; }" : "=r"(r) : "l"(p));
    return r;
}
__device__ __forceinline__ void ldsm4(uint32_t r[4], uint32_t addr) {
    asm volatile("ldmatrix.sync.aligned.m8n8.x4.shared.b16 {%0,%1,%2,%3}, [%4];"
                 : "=r"(r[0]), "=r"(r[1]), "=r"(r[2]), "=r"(r[3]) : "r"(addr));
}
__device__ __forceinline__ void mma_f16(float c[4], const uint32_t a[4], uint32_t b0, uint32_t b1) {
    asm volatile("mma.sync.aligned.m16n8k16.row.col.f32.f16.f16.f32 "
                 "{%0,%1,%2,%3}, {%4,%5,%6,%7}, {%8,%9}, {%0,%1,%2,%3};"
                 : "+f"(c[0]), "+f"(c[1]), "+f"(c[2]), "+f"(c[3])
                 : "r"(a[0]), "r"(a[1]), "r"(a[2]), "r"(a[3]), "r"(b0), "r"(b1));
}
#define CP16(dst, src) asm volatile("cp.async.cg.shared.global [%0], [%1], 16;" :: "r"(dst), "l"(src))
#define CP_COMMIT()    asm volatile("cp.async.commit_group;")
#define CP_WAIT1()     asm volatile("cp.async.wait_group 1;")

// ---------------- transposes ----------------
// fp32 -> fp32 (final output path)
__global__ void tpose_k(const float* __restrict__ in, float* __restrict__ out,
                        int R, int C, long sIn, long sOut) {
    __shared__ float tile[32][33];
    const float* ib = in  + (long)blockIdx.z * sIn;
    float*       ob = out + (long)blockIdx.z * sOut;
    int c0 = blockIdx.x * 32, r0 = blockIdx.y * 32;
    #pragma unroll
    for (int y = threadIdx.y; y < 32; y += 8)
        tile[y][threadIdx.x] = ib[(long)(r0 + y) * C + c0 + threadIdx.x];
    __syncthreads();
    #pragma unroll
    for (int y = threadIdx.y; y < 32; y += 8)
        ob[(long)(c0 + y) * R + r0 + threadIdx.x] = tile[threadIdx.x][y];
}

// fp32 -> half, 3 weight sets, grid (C/32, R/32, 3*nb)
__global__ void tpose3h_k(const float* __restrict__ i0, const float* __restrict__ i1,
                          const float* __restrict__ i2,
                          __half* __restrict__ o0, __half* __restrict__ o1, __half* __restrict__ o2,
                          int R, int C, long stride, int nb) {
    __shared__ float tile[32][33];
    int z = blockIdx.z;
    int sel = z / nb, bb = z % nb;
    const float* in = (sel == 0) ? i0 : (sel == 1) ? i1 : i2;
    __half*     out = (sel == 0) ? o0 : (sel == 1) ? o1 : o2;
    const float* ib = in  + (long)bb * stride;
    __half*      ob = out + (long)bb * stride;
    int c0 = blockIdx.x * 32, r0 = blockIdx.y * 32;
    #pragma unroll
    for (int y = threadIdx.y; y < 32; y += 8)
        tile[y][threadIdx.x] = ib[(long)(r0 + y) * C + c0 + threadIdx.x];
    __syncthreads();
    #pragma unroll
    for (int y = threadIdx.y; y < 32; y += 8)
        ob[(long)(c0 + y) * R + r0 + threadIdx.x] = __float2half_rn(tile[threadIdx.x][y]);
}

// fp32 -> half single
__global__ void tposeh_k(const float* __restrict__ in, __half* __restrict__ out,
                         int R, int C, long sIn, long sOut) {
    __shared__ float tile[32][33];
    const float* ib = in  + (long)blockIdx.z * sIn;
    __half*      ob = out + (long)blockIdx.z * sOut;
    int c0 = blockIdx.x * 32, r0 = blockIdx.y * 32;
    #pragma unroll
    for (int y = threadIdx.y; y < 32; y += 8)
        tile[y][threadIdx.x] = ib[(long)(r0 + y) * C + c0 + threadIdx.x];
    __syncthreads();
    #pragma unroll
    for (int y = threadIdx.y; y < 32; y += 8)
        ob[(long)(c0 + y) * R + r0 + threadIdx.x] = __float2half_rn(tile[threadIdx.x][y]);
}

// fp32 -> fp32 AND half (x3 -> t and ht)
__global__ void tposeft_k(const float* __restrict__ in, float* __restrict__ of,
                          __half* __restrict__ oh, int R, int C, long sIn, long sOut) {
    __shared__ float tile[32][33];
    const float* ib = in + (long)blockIdx.z * sIn;
    float*       obf = of + (long)blockIdx.z * sOut;
    __half*      obh = oh + (long)blockIdx.z * sOut;
    int c0 = blockIdx.x * 32, r0 = blockIdx.y * 32;
    #pragma unroll
    for (int y = threadIdx.y; y < 32; y += 8)
        tile[y][threadIdx.x] = ib[(long)(r0 + y) * C + c0 + threadIdx.x];
    __syncthreads();
    #pragma unroll
    for (int y = threadIdx.y; y < 32; y += 8) {
        float v = tile[threadIdx.x][y];
        long o = (long)(c0 + y) * R + r0 + threadIdx.x;
        obf[o] = v;
        obh[o] = __float2half_rn(v);
    }
}

// ---------------- RMSNorm: two-phase reduce ----------------
__global__ void rms_part_k(const float* __restrict__ x, float* __restrict__ part) {
    int blk = blockIdx.x;
    int b = blk >> 5, c = blk & 31;
    const float4* xb = (const float4*)(x + (size_t)b * MD + (size_t)c * 8192);
    float s = 0.f;
    for (int i = threadIdx.x; i < 2048; i += 256) {
        float4 v = xb[i];
        s += v.x * v.x + v.y * v.y + v.z * v.z + v.w * v.w;
    }
    __shared__ float sm[8];
    for (int o = 16; o; o >>= 1) s += __shfl_xor_sync(0xffffffffu, s, o);
    if ((threadIdx.x & 31) == 0) sm[threadIdx.x >> 5] = s;
    __syncthreads();
    if (threadIdx.x < 8) {
        s = sm[threadIdx.x];
        for (int o = 4; o; o >>= 1) s += __shfl_xor_sync(0xffu, s, o);
        if (threadIdx.x == 0) part[blk] = s;
    }
}
__global__ void rms_fin_k(const float* __restrict__ part, float* __restrict__ ff) {
    int b = threadIdx.x >> 5, lane = threadIdx.x & 31;
    float s = part[b * 32 + lane];
    for (int o = 16; o; o >>= 1) s += __shfl_xor_sync(0xffffffffu, s, o);
    if (lane == 0) ff[b] = sqrtf((float)MD) * rsqrtf(s);
}
// apply -> half
__global__ void rms_apply_h_k(const float* __restrict__ x, const float* __restrict__ scale,
                              const float* __restrict__ ff, __half* __restrict__ y) {
    long i = (long)blockIdx.x * blockDim.x + threadIdx.x;
    if (i >= (long)BB * MD) return;
    int b  = (int)(i / MD);
    int md = (int)(i % MD);
    y[i] = __float2half_rn(x[i] * scale[md] * ff[b]);
}
// apply -> fp32 (x3)
__global__ void rms_apply_f_k(const float* __restrict__ x, const float* __restrict__ scale,
                              const float* __restrict__ ff, float* __restrict__ y) {
    long i = (long)blockIdx.x * blockDim.x + threadIdx.x;
    if (i >= (long)BB * MD) return;
    int b  = (int)(i / MD);
    int md = (int)(i % MD);
    y[i] = x[i] * scale[md] * ff[b];
}

// ---------------- softmax L=512: fp32 in, fp16 out (warp per row) ----------------
__global__ void softmax512m_k(const float* __restrict__ s, __half* __restrict__ p, long nrows) {
    long row = (long)blockIdx.x * (blockDim.x >> 5) + (threadIdx.x >> 5);
    if (row >= nrows) return;
    int lane = threadIdx.x & 31;
    const float4* rp = reinterpret_cast<const float4*>(s + row * 512);
    __half2* op = reinterpret_cast<__half2*>(p + row * 512);
    float4 d[4];
    #pragma unroll
    for (int j = 0; j < 4; j++) d[j] = rp[lane + 32 * j];
    float mx = -INFINITY;
    #pragma unroll
    for (int j = 0; j < 4; j++)
        mx = fmaxf(mx, fmaxf(fmaxf(d[j].x, d[j].y), fmaxf(d[j].z, d[j].w)));
    for (int o = 16; o; o >>= 1) mx = fmaxf(mx, __shfl_xor_sync(0xffffffffu, mx, o));
    float sum = 0.f;
    #pragma unroll
    for (int j = 0; j < 4; j++) {
        d[j].x = __expf(d[j].x - mx); d[j].y = __expf(d[j].y - mx);
        d[j].z = __expf(d[j].z - mx); d[j].w = __expf(d[j].w - mx);
        sum += d[j].x + d[j].y + d[j].z + d[j].w;
    }
    for (int o = 16; o; o >>= 1) sum += __shfl_xor_sync(0xffffffffu, sum, o);
    float inv = 1.f / sum;
    #pragma unroll
    for (int j = 0; j < 4; j++) {
        int e = 2 * (lane + 32 * j);          // half2 index of element 4*(lane+32j)
        op[e]     = __floats2half2_rn(d[j].x * inv, d[j].y * inv);
        op[e + 1] = __floats2half2_rn(d[j].z * inv, d[j].w * inv);
    }
}

// ---------------- generic row softmax (stage-2, L=64, fp32) ----------------
__global__ void softmax_k(float* __restrict__ s, int L, long nrows) {
    long warp = (long)blockIdx.x * (blockDim.x >> 5) + (threadIdx.x >> 5);
    if (warp >= nrows) return;
    int lane = threadIdx.x & 31;
    float* row = s + warp * (long)L;
    float mx = -INFINITY;
    for (int i = lane; i < L; i += 32) mx = fmaxf(mx, row[i]);
    for (int o = 16; o; o >>= 1) mx = fmaxf(mx, __shfl_xor_sync(0xffffffffu, mx, o));
    float sum = 0.f;
    for (int i = lane; i < L; i += 32) {
        float e = __expf(row[i] - mx);
        row[i] = e;
        sum += e;
    }
    for (int o = 16; o; o >>= 1) sum += __shfl_xor_sync(0xffffffffu, sum, o);
    float inv = 1.f / sum;
    for (int i = lane; i < L; i += 32) row[i] *= inv;
}

// ==================== fp16 mma.sync GEMM, cp.async 3-stage, all-TRANSB ====================
// C = alpha * A @ B^T (+R)(+bias), optional fused RoPE; C fp16 (HOUT) or fp32.
// A row-major [m][k] half, B row-major [n][k] half. 128x128 CTA tile, K-tile 64.
// 256 thr (2m x 4n warps), warp 64x32. M,N%128==0, K%64==0, K>=192.

#define NSTG      3
#define STG_BYTES 32768                  // A 16KB + B 16KB (half)
#define TG_SMEM   (NSTG * STG_BYTES)     // 98304

template<bool RES, bool BIAS, bool HOUT, bool ROPE>
__global__ void __launch_bounds__(256, 2) hg_k(
    const __half* __restrict__ A, int lda, long sAo, long sAi,
    const __half* __restrict__ Bm, int ldb, long sBo, long sBi,
    void*         __restrict__ Cm, int ldc, long sCo, long sCi,
    const __half* __restrict__ R, int ldr, long sRi,
    const float*  __restrict__ bias,
    int K, int inner, float alpha, int angmod, float thc)
{
    extern __shared__ uint8_t smem[];

    int z  = blockIdx.z;
    int zo = z / inner;
    int zi = z - zo * inner;
    A  += zo * sAo + zi * sAi;
    Bm += zo * sBo + zi * sBi;
    long coff = zo * sCo + zi * sCi;
    float*  Cf = (float*)Cm + coff;
    __half* Ch = (__half*)Cm + coff;
    if (RES) R += (long)zi * sRi;

    const int tid  = threadIdx.x;
    const int lane = tid & 31;
    const int wid  = tid >> 5;
    const int warpM = wid & 1;
    const int warpN = wid >> 1;
    const int m0 = blockIdx.y << 7;
    const int n0 = blockIdx.x << 7;

    const uint32_t sbase = cvta_smem_u32(smem);

    const int cA = tid & 7;     // 16B chunk (8 halves) 0..7
    const int rA = tid >> 3;    // row 0..31
    const int lr = (lane & 7) + ((lane >> 3) & 1) * 8;
    const int lc = lane >> 4;

    float acc[4][4][4];
    #pragma unroll
    for (int i = 0; i < 4; i++)
        #pragma unroll
        for (int j = 0; j < 4; j++)
            #pragma unroll
            for (int r = 0; r < 4; r++) acc[i][j][r] = 0.f;

    const int niter = K >> 6;

    #define HG_ISSUE(st, k0)                                                          \
    {                                                                                 \
        uint32_t sA = sbase + (uint32_t)(st) * STG_BYTES;                             \
        uint32_t sB = sA + 16384u;                                                    \
        _Pragma("unroll")                                                             \
        for (int g = 0; g < 4; g++) {                                                 \
            int r = rA + 32 * g;                                                      \
            uint32_t off = (uint32_t)(r * 128 + ((cA ^ (r & 7)) << 4));               \
            CP16(sA + off, &A[(long)(m0 + r) * lda + (k0) + cA * 8]);                 \
            CP16(sB + off, &Bm[(long)(n0 + r) * ldb + (k0) + cA * 8]);                \
        }                                                                             \
    }

    HG_ISSUE(0, 0);  CP_COMMIT();
    HG_ISSUE(1, 64); CP_COMMIT();

    for (int it = 0; it < niter; it++) {
        CP_WAIT1();
        __syncthreads();

        int nx = it + 2;
        if (nx < niter) { HG_ISSUE(nx % NSTG, nx << 6); }
        CP_COMMIT();   // empty group near the tail keeps wait_group<1> uniform

        int st = it % NSTG;
        const uint32_t baseA = sbase + (uint32_t)st * STG_BYTES;
        const uint32_t baseB = baseA + 16384u;
        #pragma unroll
        for (int s = 0; s < 4; s++) {           // 4 x k16 steps = 64 halves
            uint32_t af[4][4], bq[2][4];
            #pragma unroll
            for (int i = 0; i < 4; i++) {
                int row = warpM * 64 + i * 16 + lr;
                int ch  = (2 * s + lc) ^ (row & 7);
                ldsm4(af[i], baseA + (uint32_t)(row * 128 + ch * 16));
            }
            #pragma unroll
            for (int p = 0; p < 2; p++) {
                int row = warpN * 32 + p * 16 + lr;
                int ch  = (2 * s + lc) ^ (row & 7);
                ldsm4(bq[p], baseB + (uint32_t)(row * 128 + ch * 16));
            }
            #pragma unroll
            for (int i = 0; i < 4; i++)
                #pragma unroll
                for (int j = 0; j < 4; j++)
                    mma_f16(acc[i][j], af[i], bq[j >> 1][j & 1], bq[j >> 1][2 + (j & 1)]);
        }
    }
    #undef HG_ISSUE

    // --- epilogue: alpha, (RoPE), (residual/bias), store fp16 or fp32 ---
    const int g8 = lane >> 2;
    const int t4 = lane & 3;
    #pragma unroll
    for (int i = 0; i < 4; i++) {
        int mrow = m0 + warpM * 64 + i * 16 + g8;
        #pragma unroll
        for (int j = 0; j < 4; j++) {
            int col = n0 + warpN * 32 + j * 8 + 2 * t4;   // always even
            float v0 = acc[i][j][0] * alpha;
            float v1 = acc[i][j][1] * alpha;
            float v2 = acc[i][j][2] * alpha;
            float v3 = acc[i][j][3] * alpha;
            if (ROPE) {
                int pair = col >> 1;
                float theta = exp2f(thc * ((float)pair - 1.0f));
                float sn0, cs0, sn1, cs1;
                sincosf((float)(mrow % angmod) * theta, &sn0, &cs0);
                sincosf((float)((mrow + 8) % angmod) * theta, &sn1, &cs1);
                float e = v0, o = v1;
                v0 = fmaf(e, cs0, o * sn0);
                v1 = fmaf(-e, sn0, o * cs0);
                e = v2; o = v3;
                v2 = fmaf(e, cs1, o * sn1);
                v3 = fmaf(-e, sn1, o * cs1);
            }
            if (RES) {
                __half2 r01 = *reinterpret_cast<const __half2*>(&R[(long)mrow * ldr + col]);
                __half2 r23 = *reinterpret_cast<const __half2*>(&R[(long)(mrow + 8) * ldr + col]);
                v0 += __low2float(r01); v1 += __high2float(r01);
                v2 += __low2float(r23); v3 += __high2float(r23);
            }
            if (BIAS) {
                v0 += bias[col]; v1 += bias[col + 1];
                v2 += bias[col]; v3 += bias[col + 1];
            }
            if (HOUT) {
                *reinterpret_cast<__half2*>(&Ch[(long)mrow * ldc + col])       = __floats2half2_rn(v0, v1);
                *reinterpret_cast<__half2*>(&Ch[(long)(mrow + 8) * ldc + col]) = __floats2half2_rn(v2, v3);
            } else {
                *reinterpret_cast<float2*>(&Cf[(long)mrow * ldc + col])       = make_float2(v0, v1);
                *reinterpret_cast<float2*>(&Cf[(long)(mrow + 8) * ldc + col]) = make_float2(v2, v3);
            }
        }
    }
}

// ================= small fp32 SGEMM: 64x64 tile (stage-2 attn) =====
template<bool TRANSB, bool RES, bool BIAS>
__global__ void __launch_bounds__(256) sgemm_k(
    const float* __restrict__ A, int lda, long sAo, long sAi,
    const float* __restrict__ Bm, int ldb, long sBo, long sBi,
    float*       __restrict__ Cm, int ldc, long sCo, long sCi,
    const float* __restrict__ R, int ldr, long sRi,
    const float* __restrict__ bias,
    int K, int inner, float alpha)
{
    int z  = blockIdx.z;
    int zo = z / inner;
    int zi = z - zo * inner;
    A  += zo * sAo + zi * sAi;
    Bm += zo * sBo + zi * sBi;
    Cm += zo * sCo + zi * sCi;
    if (RES) R += (long)zi * sRi;

    __shared__ __align__(16) float As[16][68];
    __shared__ __align__(16) float Bs[16][68];

    const int tid = threadIdx.x;
    const int m0 = blockIdx.y << 6;
    const int n0 = blockIdx.x << 6;
    const int tx = tid & 15, ty = tid >> 4;

    const int ar = tid >> 2;
    const int ac = (tid & 3) << 2;
    const int br = tid >> 4;
    const int bc = (tid & 15) << 2;

    float acc[4][4] = {};

    for (int k0 = 0; k0 < K; k0 += 16) {
        float4 av = *reinterpret_cast<const float4*>(&A[(long)(m0 + ar) * lda + k0 + ac]);
        As[ac + 0][ar] = av.x; As[ac + 1][ar] = av.y;
        As[ac + 2][ar] = av.z; As[ac + 3][ar] = av.w;
        if (!TRANSB) {
            float4 bv = *reinterpret_cast<const float4*>(&Bm[(long)(k0 + br) * ldb + n0 + bc]);
            *reinterpret_cast<float4*>(&Bs[br][bc]) = bv;
        } else {
            float4 bv = *reinterpret_cast<const float4*>(&Bm[(long)(n0 + ar) * ldb + k0 + ac]);
            Bs[ac + 0][ar] = bv.x; Bs[ac + 1][ar] = bv.y;
            Bs[ac + 2][ar] = bv.z; Bs[ac + 3][ar] = bv.w;
        }
        __syncthreads();
        #pragma unroll
        for (int k = 0; k < 16; k++) {
            float4 a4 = *reinterpret_cast<const float4*>(&As[k][ty << 2]);
            float4 b4 = *reinterpret_cast<const float4*>(&Bs[k][tx << 2]);
            float a[4] = {a4.x, a4.y, a4.z, a4.w};
            float b[4] = {b4.x, b4.y, b4.z, b4.w};
            #pragma unroll
            for (int i = 0; i < 4; i++)
                #pragma unroll
                for (int j = 0; j < 4; j++)
                    acc[i][j] = fmaf(a[i], b[j], acc[i][j]);
        }
        __syncthreads();
    }

    #pragma unroll
    for (int i = 0; i < 4; i++) {
        int m = m0 + (ty << 2) + i;
        #pragma unroll
        for (int j = 0; j < 4; j++) {
            int n = n0 + (tx << 2) + j;
            float v = acc[i][j] * alpha;
            if (RES)  v += R[(long)m * ldr + n];
            if (BIAS) v += bias[n];
            Cm[(long)m * ldc + n] = v;
        }
    }
}

// ---------------- stage-2 split-K reduce ----------------
__global__ void s2red_k(const float* __restrict__ p, float* __restrict__ o) {
    long i = (long)blockIdx.x * blockDim.x + threadIdx.x;
    if (i >= (long)BB * CC * CC) return;
    float s = 0.f;
    #pragma unroll
    for (int ks = 0; ks < 8; ks++) s += p[(long)ks * BB * CC * CC + i];
    o[i] = s;
}

// ---------------- launch ----------------
extern "C" void kernel_launch(void* const* d_in, const int* in_sizes, int n_in,
                              void* d_out, int out_size) {
    const float* x     = (const float*)d_in[0];
    const float* scale = (const float*)d_in[1];
    const float* wq    = (const float*)d_in[2];
    const float* wk    = (const float*)d_in[3];
    const float* wv    = (const float*)d_in[4];
    const float* lin_w = (const float*)d_in[5];
    const float* lin_b = (const float*)d_in[6];
    const float* twq   = (const float*)d_in[7];
    const float* twk   = (const float*)d_in[8];
    const float* twv   = (const float*)d_in[9];
    float* out = (float*)d_out;

    __half *hx1, *hq, *hk, *hvT, *hp, *hcat, *ht;
    __half *hrwqT, *hrwkT, *hrwvT, *hrlwT, *hrtwqT, *hrtwkT, *hrtwvT;
    float *s, *x2, *x3, *t, *tq, *tk, *tv, *s2, *s2p, *t2, *ff, *red;
    cudaGetSymbolAddress((void**)&hx1,  h_x1);
    cudaGetSymbolAddress((void**)&hq,   h_q);
    cudaGetSymbolAddress((void**)&hk,   h_k);
    cudaGetSymbolAddress((void**)&hvT,  h_vT);
    cudaGetSymbolAddress((void**)&hp,   h_p);
    cudaGetSymbolAddress((void**)&hcat, h_cat);
    cudaGetSymbolAddress((void**)&ht,   h_t);
    cudaGetSymbolAddress((void**)&s,    g_s);
    cudaGetSymbolAddress((void**)&x2,   g_x2);
    cudaGetSymbolAddress((void**)&x3,   g_x3);
    cudaGetSymbolAddress((void**)&t,    g_t);
    cudaGetSymbolAddress((void**)&tq,   g_tq);
    cudaGetSymbolAddress((void**)&tk,   g_tk);
    cudaGetSymbolAddress((void**)&tv,   g_tv);
    cudaGetSymbolAddress((void**)&s2,   g_s2);
    cudaGetSymbolAddress((void**)&s2p,  g_s2p);
    cudaGetSymbolAddress((void**)&t2,   g_t2);
    cudaGetSymbolAddress((void**)&ff,   g_ff);
    cudaGetSymbolAddress((void**)&red,  g_red);
    cudaGetSymbolAddress((void**)&hrwqT, h_rwqT);
    cudaGetSymbolAddress((void**)&hrwkT, h_rwkT);
    cudaGetSymbolAddress((void**)&hrwvT, h_rwvT);
    cudaGetSymbolAddress((void**)&hrlwT, h_rlwT);
    cudaGetSymbolAddress((void**)&hrtwqT, h_rtwqT);
    cudaGetSymbolAddress((void**)&hrtwkT, h_rtwkT);
    cudaGetSymbolAddress((void**)&hrtwvT, h_rtwvT);

    cudaFuncSetAttribute(hg_k<false,false,true ,true >, cudaFuncAttributeMaxDynamicSharedMemorySize, TG_SMEM);
    cudaFuncSetAttribute(hg_k<false,false,true ,false>, cudaFuncAttributeMaxDynamicSharedMemorySize, TG_SMEM);
    cudaFuncSetAttribute(hg_k<false,false,false,false>, cudaFuncAttributeMaxDynamicSharedMemorySize, TG_SMEM);
    cudaFuncSetAttribute(hg_k<false,false,false,true >, cudaFuncAttributeMaxDynamicSharedMemorySize, TG_SMEM);
    cudaFuncSetAttribute(hg_k<true ,true ,false,false>, cudaFuncAttributeMaxDynamicSharedMemorySize, TG_SMEM);

    const float th1 = -2.0f * log2f(10000.0f) / (float)DD;
    const float th2 = -2.0f * log2f(10000.0f) / (float)TDD;
    const float al1 = 1.0f / sqrtf((float)DD);
    const float al2 = 1.0f / sqrtf((float)TDD);

    // ---- weight round+transpose to fp16 [n][k] ----
    {
        dim3 b32(32, 8);
        tpose3h_k<<<dim3(DD/32, DD/32, 3*HH), b32>>>(wq, wk, wv, hrwqT, hrwkT, hrwvT,
                                                     DD, DD, (long)DD*DD, HH);
        tpose3h_k<<<dim3(TDD/32, TDD/32, 3), b32>>>(twq, twk, twv, hrtwqT, hrtwkT, hrtwvT,
                                                    TDD, TDD, 0, 1);
    }

    // ---- x1 = rmsnorm(x) -> fp16 ----
    rms_part_k<<<BB * 32, 256>>>(x, red);
    rms_fin_k<<<1, 1024>>>(red, ff);
    rms_apply_h_k<<<(BB * MD) / 256, 256>>>(x, scale, ff, hx1);

    // ---- launch 5 (ncu slot): q GEMM ----
    // q/k = x1 @ wT^T with fused RoPE; vT = rwvT @ x1^T (direct transposed V)
    {
        dim3 g(DD / 128, MM / 128, HH * BB);
        hg_k<false,false,true,true ><<<g, 256, TG_SMEM>>>(hx1, DD, 0, MD, hrwqT, DD, (long)DD*DD, 0,
                                                          hq, DD, (long)BB * MD, MD,
                                                          nullptr, 0, 0, nullptr, DD, BB, 1.f, MM, th1);
        hg_k<false,false,true,true ><<<g, 256, TG_SMEM>>>(hx1, DD, 0, MD, hrwkT, DD, (long)DD*DD, 0,
                                                          hk, DD, (long)BB * MD, MD,
                                                          nullptr, 0, 0, nullptr, DD, BB, 1.f, MM, th1);
        // vT[h,b][d][m]: A = WvT[h] [d][k], B = x1[b] [m][k] (TRANSB), C ld = MM
        dim3 gv(MM / 128, DD / 128, HH * BB);
        hg_k<false,false,true,false><<<gv, 256, TG_SMEM>>>(hrwvT, DD, (long)DD*DD, 0, hx1, DD, 0, MD,
                                                           hvT, MM, (long)BB * MD, MD,
                                                           nullptr, 0, 0, nullptr, DD, BB, 1.f, 1, 0.f);
    }

    // ---- S = (q@k^T)/sqrt(D) fp32; softmax -> fp16 P; O = P @ vT^T -> fp16 cat ----
    {
        dim3 g(MM / 128, MM / 128, HH * BB);
        hg_k<false,false,false,false><<<g, 256, TG_SMEM>>>(hq, DD, (long)BB * MD, MD,
                                                           hk, DD, (long)BB * MD, MD,
                                                           s, MM, (long)BB * MM * MM, (long)MM * MM,
                                                           nullptr, 0, 0, nullptr, DD, BB, al1, 1, 0.f);
        long nrows = (long)HH * BB * MM;
        softmax512m_k<<<(int)(nrows / 8), 256>>>(s, hp, nrows);
        dim3 g2(DD / 128, MM / 128, HH * BB);
        hg_k<false,false,true,false><<<g2, 256, TG_SMEM>>>(hp, MM, (long)BB * MM * MM, (long)MM * MM,
                                                           hvT, MM, (long)BB * MD, MD,
                                                           hcat, HH * DD, (long)DD, (long)MM * HH * DD,
                                                           nullptr, 0, 0, nullptr, MM, BB, 1.f, 1, 0.f);
    }

    // ---- lin_w transpose (needed only now) ----
    tposeh_k<<<dim3(DD/32, (HH*DD)/32, 1), dim3(32,8)>>>(lin_w, hrlwT, HH*DD, DD, 0, 0);

    // ---- x2 = x1 + cat @ rlwT^T + lin_b (fp32 out) ----
    {
        dim3 g(DD / 128, (BB * MM) / 128, 1);
        hg_k<true,true,false,false><<<g, 256, TG_SMEM>>>(hcat, HH * DD, 0, 0, hrlwT, HH * DD, 0, 0,
                                                         x2, DD, 0, 0,
                                                         hx1, DD, 0, lin_b, HH * DD, 1, 1.f, 1, 0.f);
    }

    // ---- x3 = rmsnorm(x2) fp32; t (fp32) + ht (fp16) = transpose(x3) ----
    rms_part_k<<<BB * 32, 256>>>(x2, red);
    rms_fin_k<<<1, 1024>>>(red, ff);
    rms_apply_f_k<<<(BB * MD) / 256, 256>>>(x2, scale, ff, x3);
    tposeft_k<<<dim3(DD/32, MM/32, BB), dim3(32,8)>>>(x3, t, ht, MM, DD, (long)MD, (long)MD);

    // ---- tq/tk/tv = t @ rtwT^T (fp32 out; tq,tk fused stage-2 RoPE) ----
    {
        dim3 g(TDD / 128, (BB * CC) / 128, 1);
        hg_k<false,false,false,true ><<<g, 256, TG_SMEM>>>(ht, TDD, 0, 0, hrtwqT, TDD, 0, 0, tq, TDD, 0, 0,
                                                           nullptr, 0, 0, nullptr, TDD, 1, 1.f, CC, th2);
        hg_k<false,false,false,true ><<<g, 256, TG_SMEM>>>(ht, TDD, 0, 0, hrtwkT, TDD, 0, 0, tk, TDD, 0, 0,
                                                           nullptr, 0, 0, nullptr, TDD, 1, 1.f, CC, th2);
        hg_k<false,false,false,false><<<g, 256, TG_SMEM>>>(ht, TDD, 0, 0, hrtwvT, TDD, 0, 0, tv, TDD, 0, 0,
                                                           nullptr, 0, 0, nullptr, TDD, 1, 1.f, 1, 0.f);
    }

    // ---- stage-2 attention (fp32, unchanged) ----
    {
        dim3 g(1, 1, 8 * BB);       // zo = K-split index, zi = batch
        sgemm_k<true,false,false><<<g, 256>>>(tq, TDD, 512, (long)CC * TDD,
                                              tk, TDD, 512, (long)CC * TDD,
                                              s2p, CC, (long)BB * CC * CC, (long)CC * CC,
                                              nullptr, 0, 0, nullptr, 512, BB, al2);
        s2red_k<<<(BB * CC * CC + 255) / 256, 256>>>(s2p, s2);
        softmax_k<<<(BB * CC) / 8, 256>>>(s2, CC, (long)BB * CC);
        dim3 g2(TDD / 64, 1, BB);
        sgemm_k<false,true,false><<<g2, 256>>>(s2, CC, 0, (long)CC * CC,
                                               tv, TDD, 0, (long)CC * TDD,
                                               t2, TDD, 0, (long)CC * TDD,
                                               t, TDD, (long)CC * TDD, nullptr,
                                               CC, BB, 1.f);
    }

    // ---- out = per-batch transpose of t2 back to [m][d] ----
    tpose_k<<<dim3(MM/32, DD/32, BB), dim3(32,8)>>>(t2, out, DD, MM, (long)MD, (long)MD);
}

// round 17
// speedup vs baseline: 1.7537x; 1.0026x over previous
#include <cuda_runtime.h>
#include <cuda_fp16.h>
#include <math.h>
#include <stdint.h>

// ---------------- problem constants ----------------
#define BB 32
#define MM 512
#define DD 512
#define HH 8
#define FF 8
#define CC 64           // DD / FF
#define TDD 4096        // FF * MM
#define MD (MM * DD)    // 262144

// ---------------- device scratch (no allocs allowed) ----------------
__device__ __half h_x1 [(size_t)BB * MD];
__device__ __half h_q  [(size_t)HH * BB * MD];
__device__ __half h_k  [(size_t)HH * BB * MD];
__device__ __half h_vT [(size_t)HH * BB * MD];
__device__ __half h_p  [(size_t)HH * BB * MM * MM];   // P (post-softmax), fp16
__device__ __half h_cat[(size_t)BB * MM * HH * DD];
__device__ __half h_t  [(size_t)BB * CC * TDD];
__device__ float  g_s  [(size_t)HH * BB * MM * MM];   // S logits, fp32
__device__ float  g_x2 [(size_t)BB * MD];
__device__ float  g_x3 [(size_t)BB * MD];
__device__ float  g_t  [(size_t)BB * CC * TDD];       // fp32 t for residual
__device__ float  g_tq [(size_t)BB * CC * TDD];
__device__ float  g_tk [(size_t)BB * CC * TDD];
__device__ float  g_tv [(size_t)BB * CC * TDD];
__device__ float  g_s2 [(size_t)BB * CC * CC];
__device__ float  g_s2p[(size_t)8 * BB * CC * CC];
__device__ float  g_t2 [(size_t)BB * CC * TDD];
__device__ float  g_ff [BB];
__device__ float  g_red[BB * 32];
// fp16, TRANSPOSED weight copies (B operands, [n][k] layout)
__device__ __half h_rwqT[(size_t)HH * DD * DD];
__device__ __half h_rwkT[(size_t)HH * DD * DD];
__device__ __half h_rwvT[(size_t)HH * DD * DD];
__device__ __half h_rlwT[(size_t)HH * DD * DD];      // [512][4096]
__device__ __half h_rtwqT[(size_t)TDD * TDD];
__device__ __half h_rtwkT[(size_t)TDD * TDD];
__device__ __half h_rtwvT[(size_t)TDD * TDD];

// ---------------- helpers ----------------
__device__ __forceinline__ uint32_t cvta_smem_u32(const void* p) {
    uint32_t r;
    asm("{ .reg .u64 t; cvta.to.shared.u64 t, %1; cvt.u32.u64 %0, t; }" : "=r"(r) : "l"(p));
    return r;
}
__device__ __forceinline__ void ldsm4(uint32_t r[4], uint32_t addr) {
    asm volatile("ldmatrix.sync.aligned.m8n8.x4.shared.b16 {%0,%1,%2,%3}, [%4];"
                 : "=r"(r[0]), "=r"(r[1]), "=r"(r[2]), "=r"(r[3]) : "r"(addr));
}
__device__ __forceinline__ void mma_f16(float c[4], const uint32_t a[4], uint32_t b0, uint32_t b1) {
    asm volatile("mma.sync.aligned.m16n8k16.row.col.f32.f16.f16.f32 "
                 "{%0,%1,%2,%3}, {%4,%5,%6,%7}, {%8,%9}, {%0,%1,%2,%3};"
                 : "+f"(c[0]), "+f"(c[1]), "+f"(c[2]), "+f"(c[3])
                 : "r"(a[0]), "r"(a[1]), "r"(a[2]), "r"(a[3]), "r"(b0), "r"(b1));
}
#define CP16(dst, src) asm volatile("cp.async.cg.shared.global [%0], [%1], 16;" :: "r"(dst), "l"(src))
#define CP_COMMIT()    asm volatile("cp.async.commit_group;")
#define CP_WAIT1()     asm volatile("cp.async.wait_group 1;")

// ---------------- transposes ----------------
// fp32 -> fp32 (final output path)
__global__ void tpose_k(const float* __restrict__ in, float* __restrict__ out,
                        int R, int C, long sIn, long sOut) {
    __shared__ float tile[32][33];
    const float* ib = in  + (long)blockIdx.z * sIn;
    float*       ob = out + (long)blockIdx.z * sOut;
    int c0 = blockIdx.x * 32, r0 = blockIdx.y * 32;
    #pragma unroll
    for (int y = threadIdx.y; y < 32; y += 8)
        tile[y][threadIdx.x] = ib[(long)(r0 + y) * C + c0 + threadIdx.x];
    __syncthreads();
    #pragma unroll
    for (int y = threadIdx.y; y < 32; y += 8)
        ob[(long)(c0 + y) * R + r0 + threadIdx.x] = tile[threadIdx.x][y];
}

// fp32 -> half, 3 weight sets, grid (C/32, R/32, 3*nb)
__global__ void tpose3h_k(const float* __restrict__ i0, const float* __restrict__ i1,
                          const float* __restrict__ i2,
                          __half* __restrict__ o0, __half* __restrict__ o1, __half* __restrict__ o2,
                          int R, int C, long stride, int nb) {
    __shared__ float tile[32][33];
    int z = blockIdx.z;
    int sel = z / nb, bb = z % nb;
    const float* in = (sel == 0) ? i0 : (sel == 1) ? i1 : i2;
    __half*     out = (sel == 0) ? o0 : (sel == 1) ? o1 : o2;
    const float* ib = in  + (long)bb * stride;
    __half*      ob = out + (long)bb * stride;
    int c0 = blockIdx.x * 32, r0 = blockIdx.y * 32;
    #pragma unroll
    for (int y = threadIdx.y; y < 32; y += 8)
        tile[y][threadIdx.x] = ib[(long)(r0 + y) * C + c0 + threadIdx.x];
    __syncthreads();
    #pragma unroll
    for (int y = threadIdx.y; y < 32; y += 8)
        ob[(long)(c0 + y) * R + r0 + threadIdx.x] = __float2half_rn(tile[threadIdx.x][y]);
}

// fp32 -> half single
__global__ void tposeh_k(const float* __restrict__ in, __half* __restrict__ out,
                         int R, int C, long sIn, long sOut) {
    __shared__ float tile[32][33];
    const float* ib = in  + (long)blockIdx.z * sIn;
    __half*      ob = out + (long)blockIdx.z * sOut;
    int c0 = blockIdx.x * 32, r0 = blockIdx.y * 32;
    #pragma unroll
    for (int y = threadIdx.y; y < 32; y += 8)
        tile[y][threadIdx.x] = ib[(long)(r0 + y) * C + c0 + threadIdx.x];
    __syncthreads();
    #pragma unroll
    for (int y = threadIdx.y; y < 32; y += 8)
        ob[(long)(c0 + y) * R + r0 + threadIdx.x] = __float2half_rn(tile[threadIdx.x][y]);
}

// fp32 -> fp32 AND half (x3 -> t and ht)
__global__ void tposeft_k(const float* __restrict__ in, float* __restrict__ of,
                          __half* __restrict__ oh, int R, int C, long sIn, long sOut) {
    __shared__ float tile[32][33];
    const float* ib = in + (long)blockIdx.z * sIn;
    float*       obf = of + (long)blockIdx.z * sOut;
    __half*      obh = oh + (long)blockIdx.z * sOut;
    int c0 = blockIdx.x * 32, r0 = blockIdx.y * 32;
    #pragma unroll
    for (int y = threadIdx.y; y < 32; y += 8)
        tile[y][threadIdx.x] = ib[(long)(r0 + y) * C + c0 + threadIdx.x];
    __syncthreads();
    #pragma unroll
    for (int y = threadIdx.y; y < 32; y += 8) {
        float v = tile[threadIdx.x][y];
        long o = (long)(c0 + y) * R + r0 + threadIdx.x;
        obf[o] = v;
        obh[o] = __float2half_rn(v);
    }
}

// ---------------- RMSNorm: two-phase reduce ----------------
__global__ void rms_part_k(const float* __restrict__ x, float* __restrict__ part) {
    int blk = blockIdx.x;
    int b = blk >> 5, c = blk & 31;
    const float4* xb = (const float4*)(x + (size_t)b * MD + (size_t)c * 8192);
    float s = 0.f;
    for (int i = threadIdx.x; i < 2048; i += 256) {
        float4 v = xb[i];
        s += v.x * v.x + v.y * v.y + v.z * v.z + v.w * v.w;
    }
    __shared__ float sm[8];
    for (int o = 16; o; o >>= 1) s += __shfl_xor_sync(0xffffffffu, s, o);
    if ((threadIdx.x & 31) == 0) sm[threadIdx.x >> 5] = s;
    __syncthreads();
    if (threadIdx.x < 8) {
        s = sm[threadIdx.x];
        for (int o = 4; o; o >>= 1) s += __shfl_xor_sync(0xffu, s, o);
        if (threadIdx.x == 0) part[blk] = s;
    }
}
__global__ void rms_fin_k(const float* __restrict__ part, float* __restrict__ ff) {
    int b = threadIdx.x >> 5, lane = threadIdx.x & 31;
    float s = part[b * 32 + lane];
    for (int o = 16; o; o >>= 1) s += __shfl_xor_sync(0xffffffffu, s, o);
    if (lane == 0) ff[b] = sqrtf((float)MD) * rsqrtf(s);
}
// apply -> half
__global__ void rms_apply_h_k(const float* __restrict__ x, const float* __restrict__ scale,
                              const float* __restrict__ ff, __half* __restrict__ y) {
    long i = (long)blockIdx.x * blockDim.x + threadIdx.x;
    if (i >= (long)BB * MD) return;
    int b  = (int)(i / MD);
    int md = (int)(i % MD);
    y[i] = __float2half_rn(x[i] * scale[md] * ff[b]);
}
// apply -> fp32 (x3)
__global__ void rms_apply_f_k(const float* __restrict__ x, const float* __restrict__ scale,
                              const float* __restrict__ ff, float* __restrict__ y) {
    long i = (long)blockIdx.x * blockDim.x + threadIdx.x;
    if (i >= (long)BB * MD) return;
    int b  = (int)(i / MD);
    int md = (int)(i % MD);
    y[i] = x[i] * scale[md] * ff[b];
}

// ---------------- softmax L=512: fp32 in, fp16 out (warp per row) ----------------
__global__ void softmax512m_k(const float* __restrict__ s, __half* __restrict__ p, long nrows) {
    long row = (long)blockIdx.x * (blockDim.x >> 5) + (threadIdx.x >> 5);
    if (row >= nrows) return;
    int lane = threadIdx.x & 31;
    const float4* rp = reinterpret_cast<const float4*>(s + row * 512);
    __half2* op = reinterpret_cast<__half2*>(p + row * 512);
    float4 d[4];
    #pragma unroll
    for (int j = 0; j < 4; j++) d[j] = rp[lane + 32 * j];
    float mx = -INFINITY;
    #pragma unroll
    for (int j = 0; j < 4; j++)
        mx = fmaxf(mx, fmaxf(fmaxf(d[j].x, d[j].y), fmaxf(d[j].z, d[j].w)));
    for (int o = 16; o; o >>= 1) mx = fmaxf(mx, __shfl_xor_sync(0xffffffffu, mx, o));
    float sum = 0.f;
    #pragma unroll
    for (int j = 0; j < 4; j++) {
        d[j].x = __expf(d[j].x - mx); d[j].y = __expf(d[j].y - mx);
        d[j].z = __expf(d[j].z - mx); d[j].w = __expf(d[j].w - mx);
        sum += d[j].x + d[j].y + d[j].z + d[j].w;
    }
    for (int o = 16; o; o >>= 1) sum += __shfl_xor_sync(0xffffffffu, sum, o);
    float inv = 1.f / sum;
    #pragma unroll
    for (int j = 0; j < 4; j++) {
        int e = 2 * (lane + 32 * j);          // half2 index of element 4*(lane+32j)
        op[e]     = __floats2half2_rn(d[j].x * inv, d[j].y * inv);
        op[e + 1] = __floats2half2_rn(d[j].z * inv, d[j].w * inv);
    }
}

// ---------------- generic row softmax (stage-2, L=64, fp32) ----------------
__global__ void softmax_k(float* __restrict__ s, int L, long nrows) {
    long warp = (long)blockIdx.x * (blockDim.x >> 5) + (threadIdx.x >> 5);
    if (warp >= nrows) return;
    int lane = threadIdx.x & 31;
    float* row = s + warp * (long)L;
    float mx = -INFINITY;
    for (int i = lane; i < L; i += 32) mx = fmaxf(mx, row[i]);
    for (int o = 16; o; o >>= 1) mx = fmaxf(mx, __shfl_xor_sync(0xffffffffu, mx, o));
    float sum = 0.f;
    for (int i = lane; i < L; i += 32) {
        float e = __expf(row[i] - mx);
        row[i] = e;
        sum += e;
    }
    for (int o = 16; o; o >>= 1) sum += __shfl_xor_sync(0xffffffffu, sum, o);
    float inv = 1.f / sum;
    for (int i = lane; i < L; i += 32) row[i] *= inv;
}

// ==================== fp16 mma.sync GEMM, cp.async 3-stage, all-TRANSB ====================
// C = alpha * A @ B^T (+R)(+bias), optional fused RoPE; C fp16 (HOUT) or fp32.
// A row-major [m][k] half, B row-major [n][k] half. 128x128 CTA tile, K-tile 64.
// 256 thr (2m x 4n warps), warp 64x32. M,N%128==0, K%64==0, K>=192.

#define NSTG      3
#define STG_BYTES 32768                  // A 16KB + B 16KB (half)
#define TG_SMEM   (NSTG * STG_BYTES)     // 98304

template<bool RES, bool BIAS, bool HOUT, bool ROPE>
__global__ void __launch_bounds__(256, 2) hg_k(
    const __half* __restrict__ A, int lda, long sAo, long sAi,
    const __half* __restrict__ Bm, int ldb, long sBo, long sBi,
    void*         __restrict__ Cm, int ldc, long sCo, long sCi,
    const __half* __restrict__ R, int ldr, long sRi,
    const float*  __restrict__ bias,
    int K, int inner, float alpha, int angmod, float thc)
{
    extern __shared__ uint8_t smem[];

    int z  = blockIdx.z;
    int zo = z / inner;
    int zi = z - zo * inner;
    A  += zo * sAo + zi * sAi;
    Bm += zo * sBo + zi * sBi;
    long coff = zo * sCo + zi * sCi;
    float*  Cf = (float*)Cm + coff;
    __half* Ch = (__half*)Cm + coff;
    if (RES) R += (long)zi * sRi;

    const int tid  = threadIdx.x;
    const int lane = tid & 31;
    const int wid  = tid >> 5;
    const int warpM = wid & 1;
    const int warpN = wid >> 1;
    const int m0 = blockIdx.y << 7;
    const int n0 = blockIdx.x << 7;

    const uint32_t sbase = cvta_smem_u32(smem);

    const int cA = tid & 7;     // 16B chunk (8 halves) 0..7
    const int rA = tid >> 3;    // row 0..31
    const int lr = (lane & 7) + ((lane >> 3) & 1) * 8;
    const int lc = lane >> 4;

    float acc[4][4][4];
    #pragma unroll
    for (int i = 0; i < 4; i++)
        #pragma unroll
        for (int j = 0; j < 4; j++)
            #pragma unroll
            for (int r = 0; r < 4; r++) acc[i][j][r] = 0.f;

    const int niter = K >> 6;

    #define HG_ISSUE(st, k0)                                                          \
    {                                                                                 \
        uint32_t sA = sbase + (uint32_t)(st) * STG_BYTES;                             \
        uint32_t sB = sA + 16384u;                                                    \
        _Pragma("unroll")                                                             \
        for (int g = 0; g < 4; g++) {                                                 \
            int r = rA + 32 * g;                                                      \
            uint32_t off = (uint32_t)(r * 128 + ((cA ^ (r & 7)) << 4));               \
            CP16(sA + off, &A[(long)(m0 + r) * lda + (k0) + cA * 8]);                 \
            CP16(sB + off, &Bm[(long)(n0 + r) * ldb + (k0) + cA * 8]);                \
        }                                                                             \
    }

    HG_ISSUE(0, 0);  CP_COMMIT();
    HG_ISSUE(1, 64); CP_COMMIT();

    for (int it = 0; it < niter; it++) {
        CP_WAIT1();
        __syncthreads();

        int nx = it + 2;
        if (nx < niter) { HG_ISSUE(nx % NSTG, nx << 6); }
        CP_COMMIT();   // empty group near the tail keeps wait_group<1> uniform

        int st = it % NSTG;
        const uint32_t baseA = sbase + (uint32_t)st * STG_BYTES;
        const uint32_t baseB = baseA + 16384u;
        #pragma unroll
        for (int s = 0; s < 4; s++) {           // 4 x k16 steps = 64 halves
            uint32_t af[4][4], bq[2][4];
            #pragma unroll
            for (int i = 0; i < 4; i++) {
                int row = warpM * 64 + i * 16 + lr;
                int ch  = (2 * s + lc) ^ (row & 7);
                ldsm4(af[i], baseA + (uint32_t)(row * 128 + ch * 16));
            }
            #pragma unroll
            for (int p = 0; p < 2; p++) {
                int row = warpN * 32 + p * 16 + lr;
                int ch  = (2 * s + lc) ^ (row & 7);
                ldsm4(bq[p], baseB + (uint32_t)(row * 128 + ch * 16));
            }
            #pragma unroll
            for (int i = 0; i < 4; i++)
                #pragma unroll
                for (int j = 0; j < 4; j++)
                    mma_f16(acc[i][j], af[i], bq[j >> 1][j & 1], bq[j >> 1][2 + (j & 1)]);
        }
    }
    #undef HG_ISSUE

    // --- epilogue: alpha, (RoPE), (residual/bias), store fp16 or fp32 ---
    const int g8 = lane >> 2;
    const int t4 = lane & 3;
    #pragma unroll
    for (int i = 0; i < 4; i++) {
        int mrow = m0 + warpM * 64 + i * 16 + g8;
        #pragma unroll
        for (int j = 0; j < 4; j++) {
            int col = n0 + warpN * 32 + j * 8 + 2 * t4;   // always even
            float v0 = acc[i][j][0] * alpha;
            float v1 = acc[i][j][1] * alpha;
            float v2 = acc[i][j][2] * alpha;
            float v3 = acc[i][j][3] * alpha;
            if (ROPE) {
                int pair = col >> 1;
                float theta = exp2f(thc * ((float)pair - 1.0f));
                float sn0, cs0, sn1, cs1;
                sincosf((float)(mrow % angmod) * theta, &sn0, &cs0);
                sincosf((float)((mrow + 8) % angmod) * theta, &sn1, &cs1);
                float e = v0, o = v1;
                v0 = fmaf(e, cs0, o * sn0);
                v1 = fmaf(-e, sn0, o * cs0);
                e = v2; o = v3;
                v2 = fmaf(e, cs1, o * sn1);
                v3 = fmaf(-e, sn1, o * cs1);
            }
            if (RES) {
                __half2 r01 = *reinterpret_cast<const __half2*>(&R[(long)mrow * ldr + col]);
                __half2 r23 = *reinterpret_cast<const __half2*>(&R[(long)(mrow + 8) * ldr + col]);
                v0 += __low2float(r01); v1 += __high2float(r01);
                v2 += __low2float(r23); v3 += __high2float(r23);
            }
            if (BIAS) {
                v0 += bias[col]; v1 += bias[col + 1];
                v2 += bias[col]; v3 += bias[col + 1];
            }
            if (HOUT) {
                *reinterpret_cast<__half2*>(&Ch[(long)mrow * ldc + col])       = __floats2half2_rn(v0, v1);
                *reinterpret_cast<__half2*>(&Ch[(long)(mrow + 8) * ldc + col]) = __floats2half2_rn(v2, v3);
            } else {
                *reinterpret_cast<float2*>(&Cf[(long)mrow * ldc + col])       = make_float2(v0, v1);
                *reinterpret_cast<float2*>(&Cf[(long)(mrow + 8) * ldc + col]) = make_float2(v2, v3);
            }
        }
    }
}

// ================= small fp32 SGEMM: 64x64 tile (stage-2 attn) =====
template<bool TRANSB, bool RES, bool BIAS>
__global__ void __launch_bounds__(256) sgemm_k(
    const float* __restrict__ A, int lda, long sAo, long sAi,
    const float* __restrict__ Bm, int ldb, long sBo, long sBi,
    float*       __restrict__ Cm, int ldc, long sCo, long sCi,
    const float* __restrict__ R, int ldr, long sRi,
    const float* __restrict__ bias,
    int K, int inner, float alpha)
{
    int z  = blockIdx.z;
    int zo = z / inner;
    int zi = z - zo * inner;
    A  += zo * sAo + zi * sAi;
    Bm += zo * sBo + zi * sBi;
    Cm += zo * sCo + zi * sCi;
    if (RES) R += (long)zi * sRi;

    __shared__ __align__(16) float As[16][68];
    __shared__ __align__(16) float Bs[16][68];

    const int tid = threadIdx.x;
    const int m0 = blockIdx.y << 6;
    const int n0 = blockIdx.x << 6;
    const int tx = tid & 15, ty = tid >> 4;

    const int ar = tid >> 2;
    const int ac = (tid & 3) << 2;
    const int br = tid >> 4;
    const int bc = (tid & 15) << 2;

    float acc[4][4] = {};

    for (int k0 = 0; k0 < K; k0 += 16) {
        float4 av = *reinterpret_cast<const float4*>(&A[(long)(m0 + ar) * lda + k0 + ac]);
        As[ac + 0][ar] = av.x; As[ac + 1][ar] = av.y;
        As[ac + 2][ar] = av.z; As[ac + 3][ar] = av.w;
        if (!TRANSB) {
            float4 bv = *reinterpret_cast<const float4*>(&Bm[(long)(k0 + br) * ldb + n0 + bc]);
            *reinterpret_cast<float4*>(&Bs[br][bc]) = bv;
        } else {
            float4 bv = *reinterpret_cast<const float4*>(&Bm[(long)(n0 + ar) * ldb + k0 + ac]);
            Bs[ac + 0][ar] = bv.x; Bs[ac + 1][ar] = bv.y;
            Bs[ac + 2][ar] = bv.z; Bs[ac + 3][ar] = bv.w;
        }
        __syncthreads();
        #pragma unroll
        for (int k = 0; k < 16; k++) {
            float4 a4 = *reinterpret_cast<const float4*>(&As[k][ty << 2]);
            float4 b4 = *reinterpret_cast<const float4*>(&Bs[k][tx << 2]);
            float a[4] = {a4.x, a4.y, a4.z, a4.w};
            float b[4] = {b4.x, b4.y, b4.z, b4.w};
            #pragma unroll
            for (int i = 0; i < 4; i++)
                #pragma unroll
                for (int j = 0; j < 4; j++)
                    acc[i][j] = fmaf(a[i], b[j], acc[i][j]);
        }
        __syncthreads();
    }

    #pragma unroll
    for (int i = 0; i < 4; i++) {
        int m = m0 + (ty << 2) + i;
        #pragma unroll
        for (int j = 0; j < 4; j++) {
            int n = n0 + (tx << 2) + j;
            float v = acc[i][j] * alpha;
            if (RES)  v += R[(long)m * ldr + n];
            if (BIAS) v += bias[n];
            Cm[(long)m * ldc + n] = v;
        }
    }
}

// ---------------- stage-2 split-K reduce ----------------
__global__ void s2red_k(const float* __restrict__ p, float* __restrict__ o) {
    long i = (long)blockIdx.x * blockDim.x + threadIdx.x;
    if (i >= (long)BB * CC * CC) return;
    float s = 0.f;
    #pragma unroll
    for (int ks = 0; ks < 8; ks++) s += p[(long)ks * BB * CC * CC + i];
    o[i] = s;
}

// ---------------- launch ----------------
extern "C" void kernel_launch(void* const* d_in, const int* in_sizes, int n_in,
                              void* d_out, int out_size) {
    const float* x     = (const float*)d_in[0];
    const float* scale = (const float*)d_in[1];
    const float* wq    = (const float*)d_in[2];
    const float* wk    = (const float*)d_in[3];
    const float* wv    = (const float*)d_in[4];
    const float* lin_w = (const float*)d_in[5];
    const float* lin_b = (const float*)d_in[6];
    const float* twq   = (const float*)d_in[7];
    const float* twk   = (const float*)d_in[8];
    const float* twv   = (const float*)d_in[9];
    float* out = (float*)d_out;

    __half *hx1, *hq, *hk, *hvT, *hp, *hcat, *ht;
    __half *hrwqT, *hrwkT, *hrwvT, *hrlwT, *hrtwqT, *hrtwkT, *hrtwvT;
    float *s, *x2, *x3, *t, *tq, *tk, *tv, *s2, *s2p, *t2, *ff, *red;
    cudaGetSymbolAddress((void**)&hx1,  h_x1);
    cudaGetSymbolAddress((void**)&hq,   h_q);
    cudaGetSymbolAddress((void**)&hk,   h_k);
    cudaGetSymbolAddress((void**)&hvT,  h_vT);
    cudaGetSymbolAddress((void**)&hp,   h_p);
    cudaGetSymbolAddress((void**)&hcat, h_cat);
    cudaGetSymbolAddress((void**)&ht,   h_t);
    cudaGetSymbolAddress((void**)&s,    g_s);
    cudaGetSymbolAddress((void**)&x2,   g_x2);
    cudaGetSymbolAddress((void**)&x3,   g_x3);
    cudaGetSymbolAddress((void**)&t,    g_t);
    cudaGetSymbolAddress((void**)&tq,   g_tq);
    cudaGetSymbolAddress((void**)&tk,   g_tk);
    cudaGetSymbolAddress((void**)&tv,   g_tv);
    cudaGetSymbolAddress((void**)&s2,   g_s2);
    cudaGetSymbolAddress((void**)&s2p,  g_s2p);
    cudaGetSymbolAddress((void**)&t2,   g_t2);
    cudaGetSymbolAddress((void**)&ff,   g_ff);
    cudaGetSymbolAddress((void**)&red,  g_red);
    cudaGetSymbolAddress((void**)&hrwqT, h_rwqT);
    cudaGetSymbolAddress((void**)&hrwkT, h_rwkT);
    cudaGetSymbolAddress((void**)&hrwvT, h_rwvT);
    cudaGetSymbolAddress((void**)&hrlwT, h_rlwT);
    cudaGetSymbolAddress((void**)&hrtwqT, h_rtwqT);
    cudaGetSymbolAddress((void**)&hrtwkT, h_rtwkT);
    cudaGetSymbolAddress((void**)&hrtwvT, h_rtwvT);

    cudaFuncSetAttribute(hg_k<false,false,true ,true >, cudaFuncAttributeMaxDynamicSharedMemorySize, TG_SMEM);
    cudaFuncSetAttribute(hg_k<false,false,true ,false>, cudaFuncAttributeMaxDynamicSharedMemorySize, TG_SMEM);
    cudaFuncSetAttribute(hg_k<false,false,false,false>, cudaFuncAttributeMaxDynamicSharedMemorySize, TG_SMEM);
    cudaFuncSetAttribute(hg_k<false,false,false,true >, cudaFuncAttributeMaxDynamicSharedMemorySize, TG_SMEM);
    cudaFuncSetAttribute(hg_k<true ,true ,false,false>, cudaFuncAttributeMaxDynamicSharedMemorySize, TG_SMEM);

    const float th1 = -2.0f * log2f(10000.0f) / (float)DD;
    const float th2 = -2.0f * log2f(10000.0f) / (float)TDD;
    const float al1 = 1.0f / sqrtf((float)DD);
    const float al2 = 1.0f / sqrtf((float)TDD);

    // ---- weight round+transpose to fp16 [n][k] ----
    {
        dim3 b32(32, 8);
        tpose3h_k<<<dim3(DD/32, DD/32, 3*HH), b32>>>(wq, wk, wv, hrwqT, hrwkT, hrwvT,
                                                     DD, DD, (long)DD*DD, HH);
        tpose3h_k<<<dim3(TDD/32, TDD/32, 3), b32>>>(twq, twk, twv, hrtwqT, hrtwkT, hrtwvT,
                                                    TDD, TDD, 0, 1);
    }

    // ---- x1 = rmsnorm(x) -> fp16 ----
    rms_part_k<<<BB * 32, 256>>>(x, red);
    rms_fin_k<<<1, 1024>>>(red, ff);
    rms_apply_h_k<<<(BB * MD) / 256, 256>>>(x, scale, ff, hx1);

    // ---- launch 5 (ncu slot): q GEMM ----
    // q/k = x1 @ wT^T with fused RoPE; vT = rwvT @ x1^T (direct transposed V)
    {
        dim3 g(DD / 128, MM / 128, HH * BB);
        hg_k<false,false,true,true ><<<g, 256, TG_SMEM>>>(hx1, DD, 0, MD, hrwqT, DD, (long)DD*DD, 0,
                                                          hq, DD, (long)BB * MD, MD,
                                                          nullptr, 0, 0, nullptr, DD, BB, 1.f, MM, th1);
        hg_k<false,false,true,true ><<<g, 256, TG_SMEM>>>(hx1, DD, 0, MD, hrwkT, DD, (long)DD*DD, 0,
                                                          hk, DD, (long)BB * MD, MD,
                                                          nullptr, 0, 0, nullptr, DD, BB, 1.f, MM, th1);
        // vT[h,b][d][m]: A = WvT[h] [d][k], B = x1[b] [m][k] (TRANSB), C ld = MM
        dim3 gv(MM / 128, DD / 128, HH * BB);
        hg_k<false,false,true,false><<<gv, 256, TG_SMEM>>>(hrwvT, DD, (long)DD*DD, 0, hx1, DD, 0, MD,
                                                           hvT, MM, (long)BB * MD, MD,
                                                           nullptr, 0, 0, nullptr, DD, BB, 1.f, 1, 0.f);
    }

    // ---- S = (q@k^T)/sqrt(D) fp32; softmax -> fp16 P; O = P @ vT^T -> fp16 cat ----
    {
        dim3 g(MM / 128, MM / 128, HH * BB);
        hg_k<false,false,false,false><<<g, 256, TG_SMEM>>>(hq, DD, (long)BB * MD, MD,
                                                           hk, DD, (long)BB * MD, MD,
                                                           s, MM, (long)BB * MM * MM, (long)MM * MM,
                                                           nullptr, 0, 0, nullptr, DD, BB, al1, 1, 0.f);
        long nrows = (long)HH * BB * MM;
        softmax512m_k<<<(int)(nrows / 8), 256>>>(s, hp, nrows);
        dim3 g2(DD / 128, MM / 128, HH * BB);
        hg_k<false,false,true,false><<<g2, 256, TG_SMEM>>>(hp, MM, (long)BB * MM * MM, (long)MM * MM,
                                                           hvT, MM, (long)BB * MD, MD,
                                                           hcat, HH * DD, (long)DD, (long)MM * HH * DD,
                                                           nullptr, 0, 0, nullptr, MM, BB, 1.f, 1, 0.f);
    }

    // ---- lin_w transpose (needed only now) ----
    tposeh_k<<<dim3(DD/32, (HH*DD)/32, 1), dim3(32,8)>>>(lin_w, hrlwT, HH*DD, DD, 0, 0);

    // ---- x2 = x1 + cat @ rlwT^T + lin_b (fp32 out) ----
    {
        dim3 g(DD / 128, (BB * MM) / 128, 1);
        hg_k<true,true,false,false><<<g, 256, TG_SMEM>>>(hcat, HH * DD, 0, 0, hrlwT, HH * DD, 0, 0,
                                                         x2, DD, 0, 0,
                                                         hx1, DD, 0, lin_b, HH * DD, 1, 1.f, 1, 0.f);
    }

    // ---- x3 = rmsnorm(x2) fp32; t (fp32) + ht (fp16) = transpose(x3) ----
    rms_part_k<<<BB * 32, 256>>>(x2, red);
    rms_fin_k<<<1, 1024>>>(red, ff);
    rms_apply_f_k<<<(BB * MD) / 256, 256>>>(x2, scale, ff, x3);
    tposeft_k<<<dim3(DD/32, MM/32, BB), dim3(32,8)>>>(x3, t, ht, MM, DD, (long)MD, (long)MD);

    // ---- tq/tk/tv = t @ rtwT^T (fp32 out; tq,tk fused stage-2 RoPE) ----
    {
        dim3 g(TDD / 128, (BB * CC) / 128, 1);
        hg_k<false,false,false,true ><<<g, 256, TG_SMEM>>>(ht, TDD, 0, 0, hrtwqT, TDD, 0, 0, tq, TDD, 0, 0,
                                                           nullptr, 0, 0, nullptr, TDD, 1, 1.f, CC, th2);
        hg_k<false,false,false,true ><<<g, 256, TG_SMEM>>>(ht, TDD, 0, 0, hrtwkT, TDD, 0, 0, tk, TDD, 0, 0,
                                                           nullptr, 0, 0, nullptr, TDD, 1, 1.f, CC, th2);
        hg_k<false,false,false,false><<<g, 256, TG_SMEM>>>(ht, TDD, 0, 0, hrtwvT, TDD, 0, 0, tv, TDD, 0, 0,
                                                           nullptr, 0, 0, nullptr, TDD, 1, 1.f, 1, 0.f);
    }

    // ---- stage-2 attention (fp32, unchanged) ----
    {
        dim3 g(1, 1, 8 * BB);       // zo = K-split index, zi = batch
        sgemm_k<true,false,false><<<g, 256>>>(tq, TDD, 512, (long)CC * TDD,
                                              tk, TDD, 512, (long)CC * TDD,
                                              s2p, CC, (long)BB * CC * CC, (long)CC * CC,
                                              nullptr, 0, 0, nullptr, 512, BB, al2);
        s2red_k<<<(BB * CC * CC + 255) / 256, 256>>>(s2p, s2);
        softmax_k<<<(BB * CC) / 8, 256>>>(s2, CC, (long)BB * CC);
        dim3 g2(TDD / 64, 1, BB);
        sgemm_k<false,true,false><<<g2, 256>>>(s2, CC, 0, (long)CC * CC,
                                               tv, TDD, 0, (long)CC * TDD,
                                               t2, TDD, 0, (long)CC * TDD,
                                               t, TDD, (long)CC * TDD, nullptr,
                                               CC, BB, 1.f);
    }

    // ---- out = per-batch transpose of t2 back to [m][d] ----
    tpose_k<<<dim3(MM/32, DD/32, BB), dim3(32,8)>>>(t2, out, DD, MM, (long)MD, (long)MD);
}